// round 9
// baseline (speedup 1.0000x reference)
#include <cuda_runtime.h>
#include <cuda_bf16.h>

// ---------------------------------------------------------------------------
// GatedDeltaNet (B=2,T=4096,D=1024,H=16,DK=DV=64,KS=4)
// Round 9: rec -> 256 thr/CTA, 32 cols/CTA, 64 CTAs (2 warps per SMSP to
// hide the serial-chain latency). 2-step lookahead kept. GEMMs unchanged.
// ---------------------------------------------------------------------------

#define TDIM 4096
#define BDIM 2
#define HDIM 16
#define DDIM 1024
#define MROWS (BDIM * TDIM)
#define STAGE 8

typedef unsigned long long ull;
typedef unsigned int uint;

static constexpr size_t NM   = (size_t)MROWS * DDIM;
static constexpr size_t OF_Q  = 0;
static constexpr size_t OF_K  = 1 * NM;
static constexpr size_t OF_V  = 2 * NM;
static constexpr size_t OF_QN = 3 * NM;
static constexpr size_t OF_KN = 4 * NM;
static constexpr size_t OF_VN = 5 * NM;
static constexpr size_t OF_G  = 6 * NM;
static constexpr size_t OF_O  = 7 * NM;
static constexpr size_t OF_OG = 8 * NM;
static constexpr size_t OF_XG = 9 * NM;
static constexpr size_t OF_A  = OF_XG + (size_t)MROWS * 512;
static constexpr size_t OF_B  = OF_A + (size_t)MROWS * HDIM;
static constexpr size_t SCRATCH_FLOATS = OF_B + (size_t)MROWS * HDIM;

__device__ float g_scratch[SCRATCH_FLOATS];

__device__ __forceinline__ float sigmoidf_(float x) {
    return 1.f / (1.f + __expf(-x));
}

__device__ __forceinline__ ull fma2_(ull a, ull b, ull c) {
    ull d;
    asm("fma.rn.f32x2 %0, %1, %2, %3;" : "=l"(d) : "l"(a), "l"(b), "l"(c));
    return d;
}
__device__ __forceinline__ ull mul2_(ull a, ull b) {
    ull d;
    asm("mul.rn.f32x2 %0, %1, %2;" : "=l"(d) : "l"(a), "l"(b));
    return d;
}
__device__ __forceinline__ ull pack2_(float x) {
    ull r;
    asm("mov.b64 %0, {%1, %1};" : "=l"(r) : "r"(__float_as_uint(x)));
    return r;
}
__device__ __forceinline__ float hadd2_(ull a) {
    unsigned lo, hi;
    asm("mov.b64 {%0, %1}, %2;" : "=r"(lo), "=r"(hi) : "l"(a));
    return __uint_as_float(lo) + __uint_as_float(hi);
}

__device__ __forceinline__ void mma_bf16(float c[4],
    uint a0, uint a1, uint a2, uint a3, uint b0, uint b1)
{
    asm volatile(
        "mma.sync.aligned.m16n8k16.row.col.f32.bf16.bf16.f32 "
        "{%0,%1,%2,%3},{%4,%5,%6,%7},{%8,%9},{%0,%1,%2,%3};"
        : "+f"(c[0]), "+f"(c[1]), "+f"(c[2]), "+f"(c[3])
        : "r"(a0), "r"(a1), "r"(a2), "r"(a3), "r"(b0), "r"(b1));
}
__device__ __forceinline__ void ldsm_x4(uint& r0, uint& r1, uint& r2, uint& r3,
                                        const void* p)
{
    uint a = (uint)__cvta_generic_to_shared(p);
    asm volatile("ldmatrix.sync.aligned.m8n8.x4.shared.b16 {%0,%1,%2,%3},[%4];"
                 : "=r"(r0), "=r"(r1), "=r"(r2), "=r"(r3) : "r"(a));
}
__device__ __forceinline__ void ldsm_x2t(uint& r0, uint& r1, const void* p)
{
    uint a = (uint)__cvta_generic_to_shared(p);
    asm volatile("ldmatrix.sync.aligned.m8n8.x2.trans.shared.b16 {%0,%1},[%2];"
                 : "=r"(r0), "=r"(r1) : "r"(a));
}
__device__ __forceinline__ void split4(float4 v, uint& h01, uint& h23,
                                       uint& l01, uint& l23)
{
    __nv_bfloat162 h01b = __floats2bfloat162_rn(v.x, v.y);
    __nv_bfloat162 h23b = __floats2bfloat162_rn(v.z, v.w);
    float r0 = v.x - __bfloat162float(h01b.x);
    float r1 = v.y - __bfloat162float(h01b.y);
    float r2 = v.z - __bfloat162float(h23b.x);
    float r3 = v.w - __bfloat162float(h23b.y);
    __nv_bfloat162 l01b = __floats2bfloat162_rn(r0, r1);
    __nv_bfloat162 l23b = __floats2bfloat162_rn(r2, r3);
    h01 = *(uint*)&h01b;  h23 = *(uint*)&h23b;
    l01 = *(uint*)&l01b;  l23 = *(uint*)&l23b;
}

#define A_STRIDE 12
#define B_STRIDE 68

__global__ __launch_bounds__(256) void gemm_tc(
    const float* __restrict__ Aext, size_t Aoff,
    const float* __restrict__ W,
    float* __restrict__ Cext, size_t Coff,
    int M, int N, int K, int act)
{
    const float* A = Aext ? Aext : (const float*)g_scratch + Aoff;
    float*       C = Cext ? Cext : g_scratch + Coff;

    __shared__ __align__(16) uint As[2][2][128][A_STRIDE];
    __shared__ __align__(16) uint Bs[2][2][16][B_STRIDE];

    const int tid  = threadIdx.x;
    const int brow = blockIdx.y * 128;
    const int bcol = blockIdx.x * 128;

    const int lane = tid & 31;
    const int warp = tid >> 5;
    const int wm   = warp >> 2;
    const int wn   = warp & 3;
    const int gid  = lane >> 2;
    const int tig  = lane & 3;

    const int am0 = tid >> 2;
    const int ak0 = (tid & 3) << 2;
    const int bk0 = tid >> 5;
    const int bn0 = (tid & 31) << 2;

    const float* ApA = A + (size_t)(brow + am0) * K + ak0;
    const float* ApB = ApA + (size_t)64 * K;
    const float* BpA = W + (size_t)bk0 * N + bcol + bn0;
    const float* BpB = BpA + (size_t)8 * N;

    float acc[4][4][4];
#pragma unroll
    for (int i = 0; i < 4; i++)
#pragma unroll
        for (int j = 0; j < 4; j++)
#pragma unroll
            for (int c = 0; c < 4; c++) acc[i][j][c] = 0.f;

    const int a_lrow = lane & 15;
    const int a_koff = (lane >> 4) * 4;
    const int b_lrow = lane & 15;

    float4 avA, avB, bvA, bvB;
    avA = *(const float4*)(ApA);
    avB = *(const float4*)(ApB);
    bvA = *(const float4*)(BpA);
    bvB = *(const float4*)(BpB);
    {
        uint h01, h23, l01, l23;
        split4(avA, h01, h23, l01, l23);
        *(uint2*)&As[0][0][am0][ak0 >> 1]      = make_uint2(h01, h23);
        *(uint2*)&As[0][1][am0][ak0 >> 1]      = make_uint2(l01, l23);
        split4(avB, h01, h23, l01, l23);
        *(uint2*)&As[0][0][am0 + 64][ak0 >> 1] = make_uint2(h01, h23);
        *(uint2*)&As[0][1][am0 + 64][ak0 >> 1] = make_uint2(l01, l23);
        split4(bvA, h01, h23, l01, l23);
        *(uint2*)&Bs[0][0][bk0][bn0 >> 1]      = make_uint2(h01, h23);
        *(uint2*)&Bs[0][1][bk0][bn0 >> 1]      = make_uint2(l01, l23);
        split4(bvB, h01, h23, l01, l23);
        *(uint2*)&Bs[0][0][bk0 + 8][bn0 >> 1]  = make_uint2(h01, h23);
        *(uint2*)&Bs[0][1][bk0 + 8][bn0 >> 1]  = make_uint2(l01, l23);
    }
    __syncthreads();

    const int nk = K >> 4;
    for (int kt = 0; kt < nk; kt++) {
        const int buf = kt & 1;
        if (kt + 1 < nk) {
            const int ko = (kt + 1) << 4;
            avA = *(const float4*)(ApA + ko);
            avB = *(const float4*)(ApB + ko);
            bvA = *(const float4*)(BpA + (size_t)ko * N);
            bvB = *(const float4*)(BpB + (size_t)ko * N);
        }

        uint Ah[4][4], Al[4][4], Bh[4][2], Bl[4][2];
#pragma unroll
        for (int mt = 0; mt < 4; mt++) {
            int row = wm * 64 + mt * 16 + a_lrow;
            ldsm_x4(Ah[mt][0], Ah[mt][1], Ah[mt][2], Ah[mt][3],
                    &As[buf][0][row][a_koff]);
            ldsm_x4(Al[mt][0], Al[mt][1], Al[mt][2], Al[mt][3],
                    &As[buf][1][row][a_koff]);
        }
#pragma unroll
        for (int nt = 0; nt < 4; nt++) {
            int nu = wn * 16 + nt * 4;
            ldsm_x2t(Bh[nt][0], Bh[nt][1], &Bs[buf][0][b_lrow][nu]);
            ldsm_x2t(Bl[nt][0], Bl[nt][1], &Bs[buf][1][b_lrow][nu]);
        }

#pragma unroll
        for (int mt = 0; mt < 4; mt++) {
#pragma unroll
            for (int nt = 0; nt < 4; nt++) {
                mma_bf16(acc[mt][nt], Ah[mt][0], Ah[mt][1], Ah[mt][2], Ah[mt][3],
                         Bh[nt][0], Bh[nt][1]);
                mma_bf16(acc[mt][nt], Ah[mt][0], Ah[mt][1], Ah[mt][2], Ah[mt][3],
                         Bl[nt][0], Bl[nt][1]);
                mma_bf16(acc[mt][nt], Al[mt][0], Al[mt][1], Al[mt][2], Al[mt][3],
                         Bh[nt][0], Bh[nt][1]);
            }
        }

        if (kt + 1 < nk) {
            const int nb = buf ^ 1;
            uint h01, h23, l01, l23;
            split4(avA, h01, h23, l01, l23);
            *(uint2*)&As[nb][0][am0][ak0 >> 1]      = make_uint2(h01, h23);
            *(uint2*)&As[nb][1][am0][ak0 >> 1]      = make_uint2(l01, l23);
            split4(avB, h01, h23, l01, l23);
            *(uint2*)&As[nb][0][am0 + 64][ak0 >> 1] = make_uint2(h01, h23);
            *(uint2*)&As[nb][1][am0 + 64][ak0 >> 1] = make_uint2(l01, l23);
            split4(bvA, h01, h23, l01, l23);
            *(uint2*)&Bs[nb][0][bk0][bn0 >> 1]      = make_uint2(h01, h23);
            *(uint2*)&Bs[nb][1][bk0][bn0 >> 1]      = make_uint2(l01, l23);
            split4(bvB, h01, h23, l01, l23);
            *(uint2*)&Bs[nb][0][bk0 + 8][bn0 >> 1]  = make_uint2(h01, h23);
            *(uint2*)&Bs[nb][1][bk0 + 8][bn0 >> 1]  = make_uint2(l01, l23);
            __syncthreads();
        }
    }

#pragma unroll
    for (int mt = 0; mt < 4; mt++) {
        int row0 = brow + wm * 64 + mt * 16 + gid;
#pragma unroll
        for (int nt = 0; nt < 4; nt++) {
            int col0 = bcol + wn * 32 + nt * 8 + 2 * tig;
            float c0 = acc[mt][nt][0], c1 = acc[mt][nt][1];
            float c2 = acc[mt][nt][2], c3 = acc[mt][nt][3];
            if (act == 1) {
                c0 *= sigmoidf_(c0); c1 *= sigmoidf_(c1);
                c2 *= sigmoidf_(c2); c3 *= sigmoidf_(c3);
            } else if (act == 2) {
                c0 = sigmoidf_(c0); c1 = sigmoidf_(c1);
                c2 = sigmoidf_(c2); c3 = sigmoidf_(c3);
            }
            *(float2*)(C + (size_t)row0 * N + col0)       = make_float2(c0, c1);
            *(float2*)(C + (size_t)(row0 + 8) * N + col0) = make_float2(c2, c3);
        }
    }
}

__global__ __launch_bounds__(256) void ab_kernel(
    const float* __restrict__ x,
    const float* __restrict__ Wa, const float* __restrict__ ba,
    const float* __restrict__ Wb, const float* __restrict__ bb)
{
    int row  = blockIdx.x * 8 + (threadIdx.x >> 5);
    int lane = threadIdx.x & 31;
    const float* xr = x + (size_t)row * DDIM;
    const float* W  = (lane < 16) ? Wa : Wb;
    int h = lane & 15;

    float s0 = 0.f, s1 = 0.f, s2 = 0.f, s3 = 0.f;
#pragma unroll 4
    for (int i = 0; i < DDIM; i += 4) {
        s0 = fmaf(xr[i + 0], W[(i + 0) * HDIM + h], s0);
        s1 = fmaf(xr[i + 1], W[(i + 1) * HDIM + h], s1);
        s2 = fmaf(xr[i + 2], W[(i + 2) * HDIM + h], s2);
        s3 = fmaf(xr[i + 3], W[(i + 3) * HDIM + h], s3);
    }
    float s = (s0 + s1) + (s2 + s3);
    if (lane < 16) {
        float sg = sigmoidf_(s + ba[h]);
        g_scratch[OF_A + (size_t)row * HDIM + h] = fminf(fmaxf(sg, 0.1f), 1.0f);
    } else {
        float sg = sigmoidf_(s + bb[h]);
        g_scratch[OF_B + (size_t)row * HDIM + h] = fminf(sg, 1.0f);
    }
}

__global__ __launch_bounds__(512) void conv_kernel(
    const float* __restrict__ qcw, const float* __restrict__ qcb,
    const float* __restrict__ kcw, const float* __restrict__ kcb,
    const float* __restrict__ vcw, const float* __restrict__ vcb)
{
    int which = blockIdx.y;
    const float* w;
    const float* bias;
    size_t pre_off, out_off;
    int do_norm;
    if (which == 0) { w = qcw; bias = qcb; pre_off = OF_Q; out_off = OF_QN; do_norm = 1; }
    else if (which == 1) { w = kcw; bias = kcb; pre_off = OF_K; out_off = OF_KN; do_norm = 1; }
    else { w = vcw; bias = vcb; pre_off = OF_V; out_off = OF_VN; do_norm = 0; }

    const float* pre = (const float*)g_scratch + pre_off;
    float*       out = g_scratch + out_off;

    int row  = blockIdx.x;
    int t    = row & (TDIM - 1);
    int lane = threadIdx.x & 31;
    int h    = threadIdx.x >> 5;
    int c0   = h * 64 + lane;
    int c1   = c0 + 32;

    const float* p = pre + (size_t)row * DDIM;
    float v0 = bias[c0], v1 = bias[c1];
#pragma unroll
    for (int kk = 0; kk < 4; kk++) {
        int dt = kk - 3;
        if (t + dt >= 0) {
            const float* pr = p + (ptrdiff_t)dt * DDIM;
            v0 = fmaf(w[c0 * 4 + kk], pr[c0], v0);
            v1 = fmaf(w[c1 * 4 + kk], pr[c1], v1);
        }
    }
    v0 *= sigmoidf_(v0);
    v1 *= sigmoidf_(v1);

    if (do_norm) {
        float ss = v0 * v0 + v1 * v1;
#pragma unroll
        for (int o = 16; o > 0; o >>= 1) ss += __shfl_xor_sync(0xffffffffu, ss, o);
        float inv = 1.f / fmaxf(sqrtf(ss), 1e-6f);
        v0 *= inv; v1 *= inv;
    }
    out[(size_t)row * DDIM + c0] = v0;
    out[(size_t)row * DDIM + c1] = v1;
}

// Stage loader for 256-thread rec CTA (32 columns).
__device__ __forceinline__ void rec_load2(
    float* sk, float* sq, float* sv, float* sa, float* sb,
    const float* __restrict__ Kn, const float* __restrict__ Q,
    const float* __restrict__ V,
    const float* __restrict__ Al, const float* __restrict__ Be,
    size_t base, size_t abase, int c0, int t0, int tid)
{
    {
        int e   = (tid >> 4) & 7;
        int vec = (tid & 15) << 2;
        size_t go = base + (size_t)(t0 + e) * DDIM + vec;
        if (tid < 128)
            *(float4*)(sk + e * 64 + vec) = *(const float4*)(Kn + go);
        else
            *(float4*)(sq + e * 64 + vec) = *(const float4*)(Q + go);
    }
    if (tid < 64) {
        int ev = tid >> 3;           // 0..7
        int vv = (tid & 7) << 2;     // 0..28
        *(float4*)(sv + ev * 32 + vv) =
            *(const float4*)(V + base + (size_t)(t0 + ev) * DDIM + c0 + vv);
    } else if (tid < 72) {
        sa[tid - 64] = Al[abase + (size_t)(t0 + tid - 64) * HDIM];
    } else if (tid < 80) {
        sb[tid - 72] = Be[abase + (size_t)(t0 + tid - 72) * HDIM];
    }
}

// 2-step lookahead delta-rule recurrence, 32 cols/CTA, 256 threads.
__global__ __launch_bounds__(256) void rec_kernel()
{
    const float* Q  = g_scratch + OF_QN;
    const float* Kn = g_scratch + OF_KN;
    const float* V  = g_scratch + OF_VN;
    const float* Al = g_scratch + OF_A;
    const float* Be = g_scratch + OF_B;
    float*       O  = g_scratch + OF_O;

    int blk = blockIdx.x;
    int bh  = blk >> 1;
    int c0  = (blk & 1) * 32;
    int b   = bh >> 4, h = bh & 15;
    const size_t base  = (size_t)b * TDIM * DDIM + (size_t)h * 64;
    const size_t abase = (size_t)b * TDIM * HDIM + h;

    int tid = threadIdx.x;
    int g   = tid & 7;        // row group (rows g*8..+7)
    int jl  = tid >> 3;       // local column 0..31
    int j   = c0 + jl;
    int r0  = g * 8;

    __shared__ __align__(16) float sk[2][STAGE * 64];
    __shared__ __align__(16) float sq[2][STAGE * 64];
    __shared__ __align__(16) float sv[2][STAGE * 32];
    __shared__ float sa[2][STAGE];
    __shared__ float sb[2][STAGE];

    ull S2[4];
#pragma unroll
    for (int c = 0; c < 4; c++) S2[c] = 0ull;

    rec_load2(sk[0], sq[0], sv[0], sa[0], sb[0], Kn, Q, V, Al, Be,
              base, abase, c0, 0, tid);
    __syncthreads();

    const int nstages = TDIM / STAGE;
    for (int s = 0; s < nstages; s++) {
        const int buf = s & 1;
        if (s + 1 < nstages) {
            rec_load2(sk[buf ^ 1], sq[buf ^ 1], sv[buf ^ 1], sa[buf ^ 1], sb[buf ^ 1],
                      Kn, Q, V, Al, Be, base, abase, c0, (s + 1) * STAGE, tid);
        }
        const float* kbuf = sk[buf];
        const float* qbuf = sq[buf];
        const float* vbuf = sv[buf];

#pragma unroll
        for (int e = 0; e < STAGE; e += 2) {
            ull k0[4], k1[4], q0[4], q1[4];
            {
                const float* kp0 = kbuf + e * 64 + r0;
                const float* kp1 = kbuf + (e + 1) * 64 + r0;
                const float* qp0 = qbuf + e * 64 + r0;
                const float* qp1 = qbuf + (e + 1) * 64 + r0;
                *(ulonglong2*)(k0)     = *(const ulonglong2*)(kp0);
                *(ulonglong2*)(k0 + 2) = *(const ulonglong2*)(kp0 + 4);
                *(ulonglong2*)(k1)     = *(const ulonglong2*)(kp1);
                *(ulonglong2*)(k1 + 2) = *(const ulonglong2*)(kp1 + 4);
                *(ulonglong2*)(q0)     = *(const ulonglong2*)(qp0);
                *(ulonglong2*)(q0 + 2) = *(const ulonglong2*)(qp0 + 4);
                *(ulonglong2*)(q1)     = *(const ulonglong2*)(qp1);
                *(ulonglong2*)(q1 + 2) = *(const ulonglong2*)(qp1 + 4);
            }

            ull au0 = 0, ax1 = 0, aw0 = 0, ay1 = 0;
            ull akk = 0, ap00 = 0, ap01 = 0, ap11 = 0;
#pragma unroll
            for (int c = 0; c < 4; c++) {
                au0  = fma2_(S2[c], k0[c], au0);
                ax1  = fma2_(S2[c], k1[c], ax1);
                aw0  = fma2_(S2[c], q0[c], aw0);
                ay1  = fma2_(S2[c], q1[c], ay1);
                akk  = fma2_(k0[c], k1[c], akk);
                ap00 = fma2_(k0[c], q0[c], ap00);
                ap01 = fma2_(k0[c], q1[c], ap01);
                ap11 = fma2_(k1[c], q1[c], ap11);
            }
            float u0  = hadd2_(au0),  x1  = hadd2_(ax1);
            float w0  = hadd2_(aw0),  y1  = hadd2_(ay1);
            float kk  = hadd2_(akk),  p00 = hadd2_(ap00);
            float p01 = hadd2_(ap01), p11 = hadd2_(ap11);

            // reduce over 8 row-groups: lane bits 0..2
#pragma unroll
            for (int off = 1; off <= 4; off <<= 1) {
                u0  += __shfl_xor_sync(0xffffffffu, u0,  off);
                x1  += __shfl_xor_sync(0xffffffffu, x1,  off);
                w0  += __shfl_xor_sync(0xffffffffu, w0,  off);
                y1  += __shfl_xor_sync(0xffffffffu, y1,  off);
                kk  += __shfl_xor_sync(0xffffffffu, kk,  off);
                p00 += __shfl_xor_sync(0xffffffffu, p00, off);
                p01 += __shfl_xor_sync(0xffffffffu, p01, off);
                p11 += __shfl_xor_sync(0xffffffffu, p11, off);
            }

            float a0 = sa[buf][e],     b0 = sb[buf][e];
            float a1 = sa[buf][e + 1], b1 = sb[buf][e + 1];
            float v0 = vbuf[e * 32 + jl];
            float v1 = vbuf[(e + 1) * 32 + jl];

            float bee0 = b0 * (v0 - u0);
            float o0   = fmaf(a0, w0, bee0 * p00);
            float u1   = fmaf(a0, x1, bee0 * kk);
            float bee1 = b1 * (v1 - u1);
            float w1   = fmaf(a0, y1, bee0 * p01);
            float o1   = fmaf(a1, w1, bee1 * p11);

            ull c01 = pack2_(a0 * a1);
            ull c0k = pack2_(a1 * bee0);
            ull c1k = pack2_(bee1);
#pragma unroll
            for (int c = 0; c < 4; c++)
                S2[c] = fma2_(c01, S2[c], fma2_(c0k, k0[c], mul2_(c1k, k1[c])));

            if (g == 0) {
                size_t oo = base + (size_t)(s * STAGE + e) * DDIM + j;
                O[oo]        = o0;
                O[oo + DDIM] = o1;
            }
        }
        __syncthreads();
    }
}

__global__ __launch_bounds__(512) void post_kernel(const float* __restrict__ rms_w)
{
    const float* O  = g_scratch + OF_O;
    const float* G  = g_scratch + OF_G;
    float*       Og = g_scratch + OF_OG;

    int row  = blockIdx.x;
    int lane = threadIdx.x & 31;
    int h    = threadIdx.x >> 5;
    size_t i0 = (size_t)row * DDIM + h * 64 + lane;

    float v0 = O[i0], v1 = O[i0 + 32];
    float ss = v0 * v0 + v1 * v1;
#pragma unroll
    for (int o = 16; o > 0; o >>= 1) ss += __shfl_xor_sync(0xffffffffu, ss, o);
    float inv = rsqrtf(ss * (1.f / 64.f) + 1e-6f);

    v0 = v0 * inv * rms_w[h * 64 + lane]      * G[i0];
    v1 = v1 * inv * rms_w[h * 64 + lane + 32] * G[i0 + 32];
    Og[i0]      = v0;
    Og[i0 + 32] = v1;
}

extern "C" void kernel_launch(void* const* d_in, const int* in_sizes, int n_in,
                              void* d_out, int out_size)
{
    (void)in_sizes; (void)n_in; (void)out_size;
    const float* x   = (const float*)d_in[0];
    const float* Wq  = (const float*)d_in[1];
    const float* Wk  = (const float*)d_in[2];
    const float* Wv  = (const float*)d_in[3];
    const float* Wo  = (const float*)d_in[4];
    const float* Wa  = (const float*)d_in[5];
    const float* ba  = (const float*)d_in[6];
    const float* Wb  = (const float*)d_in[7];
    const float* bb  = (const float*)d_in[8];
    const float* Wgd = (const float*)d_in[9];
    const float* Wgu = (const float*)d_in[10];
    const float* rms = (const float*)d_in[11];
    const float* qcw = (const float*)d_in[12];
    const float* qcb = (const float*)d_in[13];
    const float* kcw = (const float*)d_in[14];
    const float* kcb = (const float*)d_in[15];
    const float* vcw = (const float*)d_in[16];
    const float* vcb = (const float*)d_in[17];
    float* out = (float*)d_out;

    dim3 g1024(1024 / 128, MROWS / 128);
    dim3 g512 (512 / 128,  MROWS / 128);

    gemm_tc<<<g1024, 256>>>(x, 0, Wq, nullptr, OF_Q, MROWS, 1024, 1024, 0);
    gemm_tc<<<g1024, 256>>>(x, 0, Wk, nullptr, OF_K, MROWS, 1024, 1024, 0);
    gemm_tc<<<g1024, 256>>>(x, 0, Wv, nullptr, OF_V, MROWS, 1024, 1024, 0);
    gemm_tc<<<g512,  256>>>(x, 0, Wgd, nullptr, OF_XG, MROWS, 512, 1024, 1);
    gemm_tc<<<g1024, 256>>>(nullptr, OF_XG, Wgu, nullptr, OF_G, MROWS, 1024, 512, 2);
    ab_kernel<<<MROWS / 8, 256>>>(x, Wa, ba, Wb, bb);
    {
        dim3 gc(MROWS, 3);
        conv_kernel<<<gc, 512>>>(qcw, qcb, kcw, kcb, vcw, vcb);
    }
    rec_kernel<<<BDIM * HDIM * 2, 256>>>();
    post_kernel<<<MROWS, 512>>>(rms);
    gemm_tc<<<g1024, 256>>>(nullptr, OF_OG, Wo, out, 0, MROWS, 1024, 1024, 0);
}

// round 10
// speedup vs baseline: 1.0142x; 1.0142x over previous
#include <cuda_runtime.h>
#include <cuda_bf16.h>

// ---------------------------------------------------------------------------
// GatedDeltaNet (B=2,T=4096,D=1024,H=16,DK=DV=64,KS=4)
// Round 10:
//   - pre-split x + all weights to bf16 hi/lo ONCE; GEMM hot loop reads bf16
//     directly (no split4 in-loop, half the global traffic)
//   - XG written split by silu epilogue; OG written split by post_kernel
//   - rec reverted to round-8 config (128thr, 4 CTAs/(b,h)) — round-9 regressed
// ---------------------------------------------------------------------------

#define TDIM 4096
#define BDIM 2
#define HDIM 16
#define DDIM 1024
#define MROWS (BDIM * TDIM)
#define STAGE 8

typedef unsigned long long ull;
typedef unsigned int uint;

static constexpr size_t NM   = (size_t)MROWS * DDIM;          // 8388608
static constexpr size_t OF_Q  = 0;
static constexpr size_t OF_K  = 1 * NM;
static constexpr size_t OF_V  = 2 * NM;
static constexpr size_t OF_QN = 3 * NM;
static constexpr size_t OF_KN = 4 * NM;
static constexpr size_t OF_VN = 5 * NM;
static constexpr size_t OF_G  = 6 * NM;
static constexpr size_t OF_O  = 7 * NM;
static constexpr size_t OF_A  = 8 * NM;                       // alpha
static constexpr size_t OF_B  = OF_A + (size_t)MROWS * HDIM;  // beta
// bf16 hi/lo arrays (uint = 2 bf16 per slot)
static constexpr size_t OF_XH   = OF_B + (size_t)MROWS * HDIM;
static constexpr size_t OF_XL   = OF_XH + NM / 2;
static constexpr size_t OF_WQH  = OF_XL + NM / 2;
static constexpr size_t OF_WQL  = OF_WQH + 524288;
static constexpr size_t OF_WKH  = OF_WQL + 524288;
static constexpr size_t OF_WKL  = OF_WKH + 524288;
static constexpr size_t OF_WVH  = OF_WKL + 524288;
static constexpr size_t OF_WVL  = OF_WVH + 524288;
static constexpr size_t OF_WGDH = OF_WVL + 524288;
static constexpr size_t OF_WGDL = OF_WGDH + 262144;
static constexpr size_t OF_WGUH = OF_WGDL + 262144;
static constexpr size_t OF_WGUL = OF_WGUH + 262144;
static constexpr size_t OF_WOH  = OF_WGUL + 262144;
static constexpr size_t OF_WOL  = OF_WOH + 524288;
static constexpr size_t OF_XGH  = OF_WOL + 524288;
static constexpr size_t OF_XGL  = OF_XGH + (size_t)MROWS * 256;
static constexpr size_t OF_OGH  = OF_XGL + (size_t)MROWS * 256;
static constexpr size_t OF_OGL  = OF_OGH + (size_t)MROWS * 512;
static constexpr size_t SCRATCH_FLOATS = OF_OGL + (size_t)MROWS * 512;

__device__ float g_scratch[SCRATCH_FLOATS];

__device__ __forceinline__ float sigmoidf_(float x) {
    return 1.f / (1.f + __expf(-x));
}
__device__ __forceinline__ ull fma2_(ull a, ull b, ull c) {
    ull d;
    asm("fma.rn.f32x2 %0, %1, %2, %3;" : "=l"(d) : "l"(a), "l"(b), "l"(c));
    return d;
}
__device__ __forceinline__ ull mul2_(ull a, ull b) {
    ull d;
    asm("mul.rn.f32x2 %0, %1, %2;" : "=l"(d) : "l"(a), "l"(b));
    return d;
}
__device__ __forceinline__ ull pack2_(float x) {
    ull r;
    asm("mov.b64 %0, {%1, %1};" : "=l"(r) : "r"(__float_as_uint(x)));
    return r;
}
__device__ __forceinline__ float hadd2_(ull a) {
    unsigned lo, hi;
    asm("mov.b64 {%0, %1}, %2;" : "=r"(lo), "=r"(hi) : "l"(a));
    return __uint_as_float(lo) + __uint_as_float(hi);
}
__device__ __forceinline__ void mma_bf16(float c[4],
    uint a0, uint a1, uint a2, uint a3, uint b0, uint b1)
{
    asm volatile(
        "mma.sync.aligned.m16n8k16.row.col.f32.bf16.bf16.f32 "
        "{%0,%1,%2,%3},{%4,%5,%6,%7},{%8,%9},{%0,%1,%2,%3};"
        : "+f"(c[0]), "+f"(c[1]), "+f"(c[2]), "+f"(c[3])
        : "r"(a0), "r"(a1), "r"(a2), "r"(a3), "r"(b0), "r"(b1));
}
__device__ __forceinline__ void ldsm_x4(uint& r0, uint& r1, uint& r2, uint& r3,
                                        const void* p)
{
    uint a = (uint)__cvta_generic_to_shared(p);
    asm volatile("ldmatrix.sync.aligned.m8n8.x4.shared.b16 {%0,%1,%2,%3},[%4];"
                 : "=r"(r0), "=r"(r1), "=r"(r2), "=r"(r3) : "r"(a));
}
__device__ __forceinline__ void ldsm_x2t(uint& r0, uint& r1, const void* p)
{
    uint a = (uint)__cvta_generic_to_shared(p);
    asm volatile("ldmatrix.sync.aligned.m8n8.x2.trans.shared.b16 {%0,%1},[%2];"
                 : "=r"(r0), "=r"(r1) : "r"(a));
}
__device__ __forceinline__ void split2(float a, float b, uint& h, uint& l)
{
    __nv_bfloat162 hb = __floats2bfloat162_rn(a, b);
    float ra = a - __bfloat162float(hb.x);
    float rb = b - __bfloat162float(hb.y);
    __nv_bfloat162 lb = __floats2bfloat162_rn(ra, rb);
    h = *(uint*)&hb;  l = *(uint*)&lb;
}

// ---------------------------------------------------------------------------
// One-time fp32 -> bf16 hi/lo split (elementwise).
// ---------------------------------------------------------------------------
__global__ __launch_bounds__(256) void split_kernel(
    const float* __restrict__ src, size_t hiOff, size_t loOff, int n4)
{
    int i = blockIdx.x * 256 + threadIdx.x;
    if (i >= n4) return;
    uint* hi = (uint*)g_scratch + hiOff;
    uint* lo = (uint*)g_scratch + loOff;
    float4 v = *(const float4*)(src + 4 * (size_t)i);
    uint h01, h23, l01, l23;
    split2(v.x, v.y, h01, l01);
    split2(v.z, v.w, h23, l23);
    *(uint2*)(hi + 2 * (size_t)i) = make_uint2(h01, h23);
    *(uint2*)(lo + 2 * (size_t)i) = make_uint2(l01, l23);
}

// ---------------------------------------------------------------------------
// Tensor-core GEMM on pre-split bf16 hi/lo operands. fp32 accum, bf16x3.
// act: 0 fp32 out, 1 silu -> bf16 hi/lo out, 2 sigmoid -> fp32 out.
// ---------------------------------------------------------------------------
#define A_STRIDE 12
#define B_STRIDE 68

__global__ __launch_bounds__(256) void gemm_tc(
    size_t ahOff, size_t alOff, size_t bhOff, size_t blOff,
    float* __restrict__ Cext, size_t cOff, size_t cOff2,
    int M, int N, int K, int act)
{
    const uint* Ahp = (const uint*)g_scratch + ahOff;
    const uint* Alp = (const uint*)g_scratch + alOff;
    const uint* Bhp = (const uint*)g_scratch + bhOff;
    const uint* Blp = (const uint*)g_scratch + blOff;

    __shared__ __align__(16) uint As[2][2][128][A_STRIDE];
    __shared__ __align__(16) uint Bs[2][2][16][B_STRIDE];

    const int tid  = threadIdx.x;
    const int brow = blockIdx.y * 128;
    const int bcol = blockIdx.x * 128;

    const int lane = tid & 31;
    const int warp = tid >> 5;
    const int wm   = warp >> 2;
    const int wn   = warp & 3;
    const int gid  = lane >> 2;
    const int tig  = lane & 3;

    const int am0 = tid >> 2;
    const int ak0 = (tid & 3) << 2;
    const int bk0 = tid >> 5;
    const int bn0 = (tid & 31) << 2;

    const int Kh = K >> 1, Nh = N >> 1;
    const uint* ApH0 = Ahp + (size_t)(brow + am0) * Kh + (ak0 >> 1);
    const uint* ApH1 = ApH0 + (size_t)64 * Kh;
    const uint* ApL0 = Alp + (size_t)(brow + am0) * Kh + (ak0 >> 1);
    const uint* ApL1 = ApL0 + (size_t)64 * Kh;
    const uint* BpH0 = Bhp + (size_t)bk0 * Nh + ((bcol + bn0) >> 1);
    const uint* BpH1 = BpH0 + (size_t)8 * Nh;
    const uint* BpL0 = Blp + (size_t)bk0 * Nh + ((bcol + bn0) >> 1);
    const uint* BpL1 = BpL0 + (size_t)8 * Nh;

    float acc[4][4][4];
#pragma unroll
    for (int i = 0; i < 4; i++)
#pragma unroll
        for (int j = 0; j < 4; j++)
#pragma unroll
            for (int c = 0; c < 4; c++) acc[i][j][c] = 0.f;

    const int a_lrow = lane & 15;
    const int a_koff = (lane >> 4) * 4;
    const int b_lrow = lane & 15;

    uint2 avH0, avH1, avL0, avL1, bvH0, bvH1, bvL0, bvL1;
    avH0 = *(const uint2*)(ApH0);  avH1 = *(const uint2*)(ApH1);
    avL0 = *(const uint2*)(ApL0);  avL1 = *(const uint2*)(ApL1);
    bvH0 = *(const uint2*)(BpH0);  bvH1 = *(const uint2*)(BpH1);
    bvL0 = *(const uint2*)(BpL0);  bvL1 = *(const uint2*)(BpL1);
    {
        *(uint2*)&As[0][0][am0][ak0 >> 1]      = avH0;
        *(uint2*)&As[0][1][am0][ak0 >> 1]      = avL0;
        *(uint2*)&As[0][0][am0 + 64][ak0 >> 1] = avH1;
        *(uint2*)&As[0][1][am0 + 64][ak0 >> 1] = avL1;
        *(uint2*)&Bs[0][0][bk0][bn0 >> 1]      = bvH0;
        *(uint2*)&Bs[0][1][bk0][bn0 >> 1]      = bvL0;
        *(uint2*)&Bs[0][0][bk0 + 8][bn0 >> 1]  = bvH1;
        *(uint2*)&Bs[0][1][bk0 + 8][bn0 >> 1]  = bvL1;
    }
    __syncthreads();

    const int nk = K >> 4;
    for (int kt = 0; kt < nk; kt++) {
        const int buf = kt & 1;
        if (kt + 1 < nk) {
            const int koA = (kt + 1) * 8;              // uints
            const size_t koB = (size_t)(kt + 1) * 16 * Nh;
            avH0 = *(const uint2*)(ApH0 + koA);
            avH1 = *(const uint2*)(ApH1 + koA);
            avL0 = *(const uint2*)(ApL0 + koA);
            avL1 = *(const uint2*)(ApL1 + koA);
            bvH0 = *(const uint2*)(BpH0 + koB);
            bvH1 = *(const uint2*)(BpH1 + koB);
            bvL0 = *(const uint2*)(BpL0 + koB);
            bvL1 = *(const uint2*)(BpL1 + koB);
        }

        uint Ah[4][4], Al[4][4], Bh[4][2], Bl[4][2];
#pragma unroll
        for (int mt = 0; mt < 4; mt++) {
            int row = wm * 64 + mt * 16 + a_lrow;
            ldsm_x4(Ah[mt][0], Ah[mt][1], Ah[mt][2], Ah[mt][3],
                    &As[buf][0][row][a_koff]);
            ldsm_x4(Al[mt][0], Al[mt][1], Al[mt][2], Al[mt][3],
                    &As[buf][1][row][a_koff]);
        }
#pragma unroll
        for (int nt = 0; nt < 4; nt++) {
            int nu = wn * 16 + nt * 4;
            ldsm_x2t(Bh[nt][0], Bh[nt][1], &Bs[buf][0][b_lrow][nu]);
            ldsm_x2t(Bl[nt][0], Bl[nt][1], &Bs[buf][1][b_lrow][nu]);
        }

#pragma unroll
        for (int mt = 0; mt < 4; mt++) {
#pragma unroll
            for (int nt = 0; nt < 4; nt++) {
                mma_bf16(acc[mt][nt], Ah[mt][0], Ah[mt][1], Ah[mt][2], Ah[mt][3],
                         Bh[nt][0], Bh[nt][1]);
                mma_bf16(acc[mt][nt], Ah[mt][0], Ah[mt][1], Ah[mt][2], Ah[mt][3],
                         Bl[nt][0], Bl[nt][1]);
                mma_bf16(acc[mt][nt], Al[mt][0], Al[mt][1], Al[mt][2], Al[mt][3],
                         Bh[nt][0], Bh[nt][1]);
            }
        }

        if (kt + 1 < nk) {
            const int nb = buf ^ 1;
            *(uint2*)&As[nb][0][am0][ak0 >> 1]      = avH0;
            *(uint2*)&As[nb][1][am0][ak0 >> 1]      = avL0;
            *(uint2*)&As[nb][0][am0 + 64][ak0 >> 1] = avH1;
            *(uint2*)&As[nb][1][am0 + 64][ak0 >> 1] = avL1;
            *(uint2*)&Bs[nb][0][bk0][bn0 >> 1]      = bvH0;
            *(uint2*)&Bs[nb][1][bk0][bn0 >> 1]      = bvL0;
            *(uint2*)&Bs[nb][0][bk0 + 8][bn0 >> 1]  = bvH1;
            *(uint2*)&Bs[nb][1][bk0 + 8][bn0 >> 1]  = bvL1;
            __syncthreads();
        }
    }

    // epilogue
    if (act == 1) {
        uint* Ch = (uint*)g_scratch + cOff;
        uint* Cl = (uint*)g_scratch + cOff2;
        const int nhalf = N >> 1;
#pragma unroll
        for (int mt = 0; mt < 4; mt++) {
            int row0 = brow + wm * 64 + mt * 16 + gid;
#pragma unroll
            for (int nt = 0; nt < 4; nt++) {
                int col0 = bcol + wn * 32 + nt * 8 + 2 * tig;
                float s0 = acc[mt][nt][0], s1 = acc[mt][nt][1];
                float s2 = acc[mt][nt][2], s3 = acc[mt][nt][3];
                s0 *= sigmoidf_(s0); s1 *= sigmoidf_(s1);
                s2 *= sigmoidf_(s2); s3 *= sigmoidf_(s3);
                uint h01, l01, h23, l23;
                split2(s0, s1, h01, l01);
                split2(s2, s3, h23, l23);
                size_t i0 = (size_t)row0 * nhalf + (col0 >> 1);
                size_t i1 = (size_t)(row0 + 8) * nhalf + (col0 >> 1);
                Ch[i0] = h01;  Cl[i0] = l01;
                Ch[i1] = h23;  Cl[i1] = l23;
            }
        }
    } else {
        float* C = Cext ? Cext : g_scratch + cOff;
#pragma unroll
        for (int mt = 0; mt < 4; mt++) {
            int row0 = brow + wm * 64 + mt * 16 + gid;
#pragma unroll
            for (int nt = 0; nt < 4; nt++) {
                int col0 = bcol + wn * 32 + nt * 8 + 2 * tig;
                float c0 = acc[mt][nt][0], c1 = acc[mt][nt][1];
                float c2 = acc[mt][nt][2], c3 = acc[mt][nt][3];
                if (act == 2) {
                    c0 = sigmoidf_(c0); c1 = sigmoidf_(c1);
                    c2 = sigmoidf_(c2); c3 = sigmoidf_(c3);
                }
                *(float2*)(C + (size_t)row0 * N + col0)       = make_float2(c0, c1);
                *(float2*)(C + (size_t)(row0 + 8) * N + col0) = make_float2(c2, c3);
            }
        }
    }
}

__global__ __launch_bounds__(256) void ab_kernel(
    const float* __restrict__ x,
    const float* __restrict__ Wa, const float* __restrict__ ba,
    const float* __restrict__ Wb, const float* __restrict__ bb)
{
    int row  = blockIdx.x * 8 + (threadIdx.x >> 5);
    int lane = threadIdx.x & 31;
    const float* xr = x + (size_t)row * DDIM;
    const float* W  = (lane < 16) ? Wa : Wb;
    int h = lane & 15;

    float s0 = 0.f, s1 = 0.f, s2 = 0.f, s3 = 0.f;
#pragma unroll 4
    for (int i = 0; i < DDIM; i += 4) {
        s0 = fmaf(xr[i + 0], W[(i + 0) * HDIM + h], s0);
        s1 = fmaf(xr[i + 1], W[(i + 1) * HDIM + h], s1);
        s2 = fmaf(xr[i + 2], W[(i + 2) * HDIM + h], s2);
        s3 = fmaf(xr[i + 3], W[(i + 3) * HDIM + h], s3);
    }
    float s = (s0 + s1) + (s2 + s3);
    if (lane < 16) {
        float sg = sigmoidf_(s + ba[h]);
        g_scratch[OF_A + (size_t)row * HDIM + h] = fminf(fmaxf(sg, 0.1f), 1.0f);
    } else {
        float sg = sigmoidf_(s + bb[h]);
        g_scratch[OF_B + (size_t)row * HDIM + h] = fminf(sg, 1.0f);
    }
}

__global__ __launch_bounds__(512) void conv_kernel(
    const float* __restrict__ qcw, const float* __restrict__ qcb,
    const float* __restrict__ kcw, const float* __restrict__ kcb,
    const float* __restrict__ vcw, const float* __restrict__ vcb)
{
    int which = blockIdx.y;
    const float* w;
    const float* bias;
    size_t pre_off, out_off;
    int do_norm;
    if (which == 0) { w = qcw; bias = qcb; pre_off = OF_Q; out_off = OF_QN; do_norm = 1; }
    else if (which == 1) { w = kcw; bias = kcb; pre_off = OF_K; out_off = OF_KN; do_norm = 1; }
    else { w = vcw; bias = vcb; pre_off = OF_V; out_off = OF_VN; do_norm = 0; }

    const float* pre = (const float*)g_scratch + pre_off;
    float*       out = g_scratch + out_off;

    int row  = blockIdx.x;
    int t    = row & (TDIM - 1);
    int lane = threadIdx.x & 31;
    int h    = threadIdx.x >> 5;
    int c0   = h * 64 + lane;
    int c1   = c0 + 32;

    const float* p = pre + (size_t)row * DDIM;
    float v0 = bias[c0], v1 = bias[c1];
#pragma unroll
    for (int kk = 0; kk < 4; kk++) {
        int dt = kk - 3;
        if (t + dt >= 0) {
            const float* pr = p + (ptrdiff_t)dt * DDIM;
            v0 = fmaf(w[c0 * 4 + kk], pr[c0], v0);
            v1 = fmaf(w[c1 * 4 + kk], pr[c1], v1);
        }
    }
    v0 *= sigmoidf_(v0);
    v1 *= sigmoidf_(v1);

    if (do_norm) {
        float ss = v0 * v0 + v1 * v1;
#pragma unroll
        for (int o = 16; o > 0; o >>= 1) ss += __shfl_xor_sync(0xffffffffu, ss, o);
        float inv = 1.f / fmaxf(sqrtf(ss), 1e-6f);
        v0 *= inv; v1 *= inv;
    }
    out[(size_t)row * DDIM + c0] = v0;
    out[(size_t)row * DDIM + c1] = v1;
}

// Round-8 rec (proven best): 128 threads, 16 cols/CTA, 2-step lookahead.
__device__ __forceinline__ void rec_load2(
    float* sk, float* sq, float* sv, float* sa, float* sb,
    const float* __restrict__ Kn, const float* __restrict__ Q,
    const float* __restrict__ V,
    const float* __restrict__ Al, const float* __restrict__ Be,
    size_t base, size_t abase, int c0, int t0, int tid)
{
    int e   = tid >> 4;
    int vec = (tid & 15) << 2;
    size_t go = base + (size_t)(t0 + e) * DDIM + vec;
    *(float4*)(sk + e * 64 + vec) = *(const float4*)(Kn + go);
    *(float4*)(sq + e * 64 + vec) = *(const float4*)(Q + go);
    if (tid < 32) {
        int ev = tid >> 2;
        int vv = (tid & 3) << 2;
        *(float4*)(sv + ev * 16 + vv) =
            *(const float4*)(V + base + (size_t)(t0 + ev) * DDIM + c0 + vv);
    } else if (tid < 40) {
        int ea = tid - 32;
        sa[ea] = Al[abase + (size_t)(t0 + ea) * HDIM];
    } else if (tid < 48) {
        int eb = tid - 40;
        sb[eb] = Be[abase + (size_t)(t0 + eb) * HDIM];
    }
}

__global__ __launch_bounds__(128) void rec_kernel()
{
    const float* Q  = g_scratch + OF_QN;
    const float* Kn = g_scratch + OF_KN;
    const float* V  = g_scratch + OF_VN;
    const float* Al = g_scratch + OF_A;
    const float* Be = g_scratch + OF_B;
    float*       O  = g_scratch + OF_O;

    int blk = blockIdx.x;
    int bh  = blk >> 2;
    int cq  = blk & 3;
    int c0  = cq * 16;
    int b   = bh >> 4, h = bh & 15;
    const size_t base  = (size_t)b * TDIM * DDIM + (size_t)h * 64;
    const size_t abase = (size_t)b * TDIM * HDIM + h;

    int tid = threadIdx.x;
    int g   = tid & 7;
    int jl  = tid >> 3;
    int j   = c0 + jl;
    int r0  = g * 8;

    __shared__ __align__(16) float sk[2][STAGE * 64];
    __shared__ __align__(16) float sq[2][STAGE * 64];
    __shared__ __align__(16) float sv[2][STAGE * 16];
    __shared__ float sa[2][STAGE];
    __shared__ float sb[2][STAGE];

    ull S2[4];
#pragma unroll
    for (int c = 0; c < 4; c++) S2[c] = 0ull;

    rec_load2(sk[0], sq[0], sv[0], sa[0], sb[0], Kn, Q, V, Al, Be,
              base, abase, c0, 0, tid);
    __syncthreads();

    const int nstages = TDIM / STAGE;
    for (int s = 0; s < nstages; s++) {
        const int buf = s & 1;
        if (s + 1 < nstages) {
            rec_load2(sk[buf ^ 1], sq[buf ^ 1], sv[buf ^ 1], sa[buf ^ 1], sb[buf ^ 1],
                      Kn, Q, V, Al, Be, base, abase, c0, (s + 1) * STAGE, tid);
        }
        const float* kbuf = sk[buf];
        const float* qbuf = sq[buf];
        const float* vbuf = sv[buf];

#pragma unroll
        for (int e = 0; e < STAGE; e += 2) {
            ull k0[4], k1[4], q0[4], q1[4];
            {
                const float* kp0 = kbuf + e * 64 + r0;
                const float* kp1 = kbuf + (e + 1) * 64 + r0;
                const float* qp0 = qbuf + e * 64 + r0;
                const float* qp1 = qbuf + (e + 1) * 64 + r0;
                *(ulonglong2*)(k0)     = *(const ulonglong2*)(kp0);
                *(ulonglong2*)(k0 + 2) = *(const ulonglong2*)(kp0 + 4);
                *(ulonglong2*)(k1)     = *(const ulonglong2*)(kp1);
                *(ulonglong2*)(k1 + 2) = *(const ulonglong2*)(kp1 + 4);
                *(ulonglong2*)(q0)     = *(const ulonglong2*)(qp0);
                *(ulonglong2*)(q0 + 2) = *(const ulonglong2*)(qp0 + 4);
                *(ulonglong2*)(q1)     = *(const ulonglong2*)(qp1);
                *(ulonglong2*)(q1 + 2) = *(const ulonglong2*)(qp1 + 4);
            }

            ull au0 = 0, ax1 = 0, aw0 = 0, ay1 = 0;
            ull akk = 0, ap00 = 0, ap01 = 0, ap11 = 0;
#pragma unroll
            for (int c = 0; c < 4; c++) {
                au0  = fma2_(S2[c], k0[c], au0);
                ax1  = fma2_(S2[c], k1[c], ax1);
                aw0  = fma2_(S2[c], q0[c], aw0);
                ay1  = fma2_(S2[c], q1[c], ay1);
                akk  = fma2_(k0[c], k1[c], akk);
                ap00 = fma2_(k0[c], q0[c], ap00);
                ap01 = fma2_(k0[c], q1[c], ap01);
                ap11 = fma2_(k1[c], q1[c], ap11);
            }
            float u0  = hadd2_(au0),  x1  = hadd2_(ax1);
            float w0  = hadd2_(aw0),  y1  = hadd2_(ay1);
            float kk  = hadd2_(akk),  p00 = hadd2_(ap00);
            float p01 = hadd2_(ap01), p11 = hadd2_(ap11);

#pragma unroll
            for (int off = 1; off <= 4; off <<= 1) {
                u0  += __shfl_xor_sync(0xffffffffu, u0,  off);
                x1  += __shfl_xor_sync(0xffffffffu, x1,  off);
                w0  += __shfl_xor_sync(0xffffffffu, w0,  off);
                y1  += __shfl_xor_sync(0xffffffffu, y1,  off);
                kk  += __shfl_xor_sync(0xffffffffu, kk,  off);
                p00 += __shfl_xor_sync(0xffffffffu, p00, off);
                p01 += __shfl_xor_sync(0xffffffffu, p01, off);
                p11 += __shfl_xor_sync(0xffffffffu, p11, off);
            }

            float a0 = sa[buf][e],     b0 = sb[buf][e];
            float a1 = sa[buf][e + 1], b1 = sb[buf][e + 1];
            float v0 = vbuf[e * 16 + jl];
            float v1 = vbuf[(e + 1) * 16 + jl];

            float bee0 = b0 * (v0 - u0);
            float o0   = fmaf(a0, w0, bee0 * p00);
            float u1   = fmaf(a0, x1, bee0 * kk);
            float bee1 = b1 * (v1 - u1);
            float w1   = fmaf(a0, y1, bee0 * p01);
            float o1   = fmaf(a1, w1, bee1 * p11);

            ull c01 = pack2_(a0 * a1);
            ull c0k = pack2_(a1 * bee0);
            ull c1k = pack2_(bee1);
#pragma unroll
            for (int c = 0; c < 4; c++)
                S2[c] = fma2_(c01, S2[c], fma2_(c0k, k0[c], mul2_(c1k, k1[c])));

            if (g == 0) {
                size_t oo = base + (size_t)(s * STAGE + e) * DDIM + j;
                O[oo]        = o0;
                O[oo + DDIM] = o1;
            }
        }
        __syncthreads();
    }
}

// RMSNorm * rms_w * gate -> OG written as bf16 hi/lo pairs.
__global__ __launch_bounds__(512) void post_kernel(const float* __restrict__ rms_w)
{
    const float* O  = g_scratch + OF_O;
    const float* G  = g_scratch + OF_G;
    uint* OGh = (uint*)g_scratch + OF_OGH;
    uint* OGl = (uint*)g_scratch + OF_OGL;

    int row  = blockIdx.x;
    int lane = threadIdx.x & 31;
    int h    = threadIdx.x >> 5;
    size_t i0 = (size_t)row * DDIM + h * 64 + 2 * lane;

    float2 vv = *(const float2*)(O + i0);
    float ss = vv.x * vv.x + vv.y * vv.y;
#pragma unroll
    for (int o = 16; o > 0; o >>= 1) ss += __shfl_xor_sync(0xffffffffu, ss, o);
    float inv = rsqrtf(ss * (1.f / 64.f) + 1e-6f);

    float2 gg = *(const float2*)(G + i0);
    float v0 = vv.x * inv * rms_w[h * 64 + 2 * lane]     * gg.x;
    float v1 = vv.y * inv * rms_w[h * 64 + 2 * lane + 1] * gg.y;
    uint hh, ll;
    split2(v0, v1, hh, ll);
    size_t oi = (size_t)row * 512 + h * 32 + lane;
    OGh[oi] = hh;
    OGl[oi] = ll;
}

extern "C" void kernel_launch(void* const* d_in, const int* in_sizes, int n_in,
                              void* d_out, int out_size)
{
    (void)in_sizes; (void)n_in; (void)out_size;
    const float* x   = (const float*)d_in[0];
    const float* Wq  = (const float*)d_in[1];
    const float* Wk  = (const float*)d_in[2];
    const float* Wv  = (const float*)d_in[3];
    const float* Wo  = (const float*)d_in[4];
    const float* Wa  = (const float*)d_in[5];
    const float* ba  = (const float*)d_in[6];
    const float* Wb  = (const float*)d_in[7];
    const float* bb  = (const float*)d_in[8];
    const float* Wgd = (const float*)d_in[9];
    const float* Wgu = (const float*)d_in[10];
    const float* rms = (const float*)d_in[11];
    const float* qcw = (const float*)d_in[12];
    const float* qcb = (const float*)d_in[13];
    const float* kcw = (const float*)d_in[14];
    const float* kcb = (const float*)d_in[15];
    const float* vcw = (const float*)d_in[16];
    const float* vcb = (const float*)d_in[17];
    float* out = (float*)d_out;

    // one-time bf16 hi/lo splits
    split_kernel<<<8192, 256>>>(x,   OF_XH,   OF_XL,   (int)(NM / 4));
    split_kernel<<<1024, 256>>>(Wq,  OF_WQH,  OF_WQL,  1024 * 1024 / 4);
    split_kernel<<<1024, 256>>>(Wk,  OF_WKH,  OF_WKL,  1024 * 1024 / 4);
    split_kernel<<<1024, 256>>>(Wv,  OF_WVH,  OF_WVL,  1024 * 1024 / 4);
    split_kernel<<<512,  256>>>(Wgd, OF_WGDH, OF_WGDL, 1024 * 512 / 4);
    split_kernel<<<512,  256>>>(Wgu, OF_WGUH, OF_WGUL, 512 * 1024 / 4);
    split_kernel<<<1024, 256>>>(Wo,  OF_WOH,  OF_WOL,  1024 * 1024 / 4);

    dim3 g1024(1024 / 128, MROWS / 128);
    dim3 g512 (512 / 128,  MROWS / 128);

    gemm_tc<<<g1024, 256>>>(OF_XH, OF_XL, OF_WQH, OF_WQL, nullptr, OF_Q, 0,
                            MROWS, 1024, 1024, 0);
    gemm_tc<<<g1024, 256>>>(OF_XH, OF_XL, OF_WKH, OF_WKL, nullptr, OF_K, 0,
                            MROWS, 1024, 1024, 0);
    gemm_tc<<<g1024, 256>>>(OF_XH, OF_XL, OF_WVH, OF_WVL, nullptr, OF_V, 0,
                            MROWS, 1024, 1024, 0);
    gemm_tc<<<g512,  256>>>(OF_XH, OF_XL, OF_WGDH, OF_WGDL, nullptr, OF_XGH, OF_XGL,
                            MROWS, 512, 1024, 1);
    gemm_tc<<<g1024, 256>>>(OF_XGH, OF_XGL, OF_WGUH, OF_WGUL, nullptr, OF_G, 0,
                            MROWS, 1024, 512, 2);
    ab_kernel<<<MROWS / 8, 256>>>(x, Wa, ba, Wb, bb);
    {
        dim3 gc(MROWS, 3);
        conv_kernel<<<gc, 512>>>(qcw, qcb, kcw, kcb, vcw, vcb);
    }
    rec_kernel<<<BDIM * HDIM * 4, 128>>>();
    post_kernel<<<MROWS, 512>>>(rms);
    gemm_tc<<<g1024, 256>>>(OF_OGH, OF_OGL, OF_WOH, OF_WOL, out, 0, 0,
                            MROWS, 1024, 1024, 0);
}

// round 11
// speedup vs baseline: 1.1865x; 1.1698x over previous
#include <cuda_runtime.h>
#include <cuda_bf16.h>

// ---------------------------------------------------------------------------
// GatedDeltaNet (B=2,T=4096,D=1024,H=16,DK=DV=64,KS=4)
// Round 11: revert to round-8 base (best). Fuse QKV gemms into one launch.
// Reorder launches so rec_kernel sits in the ncu capture slot (#4).
// ---------------------------------------------------------------------------

#define TDIM 4096
#define BDIM 2
#define HDIM 16
#define DDIM 1024
#define MROWS (BDIM * TDIM)
#define STAGE 8

typedef unsigned long long ull;
typedef unsigned int uint;

static constexpr size_t NM   = (size_t)MROWS * DDIM;
static constexpr size_t OF_Q  = 0;
static constexpr size_t OF_K  = 1 * NM;
static constexpr size_t OF_V  = 2 * NM;
static constexpr size_t OF_QN = 3 * NM;
static constexpr size_t OF_KN = 4 * NM;
static constexpr size_t OF_VN = 5 * NM;
static constexpr size_t OF_G  = 6 * NM;
static constexpr size_t OF_O  = 7 * NM;
static constexpr size_t OF_OG = 8 * NM;
static constexpr size_t OF_XG = 9 * NM;
static constexpr size_t OF_A  = OF_XG + (size_t)MROWS * 512;
static constexpr size_t OF_B  = OF_A + (size_t)MROWS * HDIM;
static constexpr size_t SCRATCH_FLOATS = OF_B + (size_t)MROWS * HDIM;

__device__ float g_scratch[SCRATCH_FLOATS];

__device__ __forceinline__ float sigmoidf_(float x) {
    return 1.f / (1.f + __expf(-x));
}
__device__ __forceinline__ ull fma2_(ull a, ull b, ull c) {
    ull d;
    asm("fma.rn.f32x2 %0, %1, %2, %3;" : "=l"(d) : "l"(a), "l"(b), "l"(c));
    return d;
}
__device__ __forceinline__ ull mul2_(ull a, ull b) {
    ull d;
    asm("mul.rn.f32x2 %0, %1, %2;" : "=l"(d) : "l"(a), "l"(b));
    return d;
}
__device__ __forceinline__ ull pack2_(float x) {
    ull r;
    asm("mov.b64 %0, {%1, %1};" : "=l"(r) : "r"(__float_as_uint(x)));
    return r;
}
__device__ __forceinline__ float hadd2_(ull a) {
    unsigned lo, hi;
    asm("mov.b64 {%0, %1}, %2;" : "=r"(lo), "=r"(hi) : "l"(a));
    return __uint_as_float(lo) + __uint_as_float(hi);
}
__device__ __forceinline__ void mma_bf16(float c[4],
    uint a0, uint a1, uint a2, uint a3, uint b0, uint b1)
{
    asm volatile(
        "mma.sync.aligned.m16n8k16.row.col.f32.bf16.bf16.f32 "
        "{%0,%1,%2,%3},{%4,%5,%6,%7},{%8,%9},{%0,%1,%2,%3};"
        : "+f"(c[0]), "+f"(c[1]), "+f"(c[2]), "+f"(c[3])
        : "r"(a0), "r"(a1), "r"(a2), "r"(a3), "r"(b0), "r"(b1));
}
__device__ __forceinline__ void ldsm_x4(uint& r0, uint& r1, uint& r2, uint& r3,
                                        const void* p)
{
    uint a = (uint)__cvta_generic_to_shared(p);
    asm volatile("ldmatrix.sync.aligned.m8n8.x4.shared.b16 {%0,%1,%2,%3},[%4];"
                 : "=r"(r0), "=r"(r1), "=r"(r2), "=r"(r3) : "r"(a));
}
__device__ __forceinline__ void ldsm_x2t(uint& r0, uint& r1, const void* p)
{
    uint a = (uint)__cvta_generic_to_shared(p);
    asm volatile("ldmatrix.sync.aligned.m8n8.x2.trans.shared.b16 {%0,%1},[%2];"
                 : "=r"(r0), "=r"(r1) : "r"(a));
}
__device__ __forceinline__ void split4(float4 v, uint& h01, uint& h23,
                                       uint& l01, uint& l23)
{
    __nv_bfloat162 h01b = __floats2bfloat162_rn(v.x, v.y);
    __nv_bfloat162 h23b = __floats2bfloat162_rn(v.z, v.w);
    float r0 = v.x - __bfloat162float(h01b.x);
    float r1 = v.y - __bfloat162float(h01b.y);
    float r2 = v.z - __bfloat162float(h23b.x);
    float r3 = v.w - __bfloat162float(h23b.y);
    __nv_bfloat162 l01b = __floats2bfloat162_rn(r0, r1);
    __nv_bfloat162 l23b = __floats2bfloat162_rn(r2, r3);
    h01 = *(uint*)&h01b;  h23 = *(uint*)&h23b;
    l01 = *(uint*)&l01b;  l23 = *(uint*)&l23b;
}

#define A_STRIDE 12
#define B_STRIDE 68

// C = A @ W, bf16x3 split in-loop, fp32 accum. Supports up to 3 fused outputs
// (Q/K/V): which = blockIdx.x / nblk selects weight + output (+which*NM).
// act: 0 none, 1 silu, 2 sigmoid.
__global__ __launch_bounds__(256) void gemm_tc(
    const float* __restrict__ Aext, size_t Aoff,
    const float* __restrict__ W0, const float* __restrict__ W1,
    const float* __restrict__ W2,
    float* __restrict__ Cext, size_t Coff, int nblk,
    int M, int N, int K, int act)
{
    const float* A = Aext ? Aext : (const float*)g_scratch + Aoff;

    const int which = blockIdx.x / nblk;
    const float* W = (which == 0) ? W0 : (which == 1) ? W1 : W2;
    float* C = Cext ? Cext : g_scratch + Coff + (size_t)which * NM;

    __shared__ __align__(16) uint As[2][2][128][A_STRIDE];
    __shared__ __align__(16) uint Bs[2][2][16][B_STRIDE];

    const int tid  = threadIdx.x;
    const int brow = blockIdx.y * 128;
    const int bcol = (blockIdx.x % nblk) * 128;

    const int lane = tid & 31;
    const int warp = tid >> 5;
    const int wm   = warp >> 2;
    const int wn   = warp & 3;
    const int gid  = lane >> 2;
    const int tig  = lane & 3;

    const int am0 = tid >> 2;
    const int ak0 = (tid & 3) << 2;
    const int bk0 = tid >> 5;
    const int bn0 = (tid & 31) << 2;

    const float* ApA = A + (size_t)(brow + am0) * K + ak0;
    const float* ApB = ApA + (size_t)64 * K;
    const float* BpA = W + (size_t)bk0 * N + bcol + bn0;
    const float* BpB = BpA + (size_t)8 * N;

    float acc[4][4][4];
#pragma unroll
    for (int i = 0; i < 4; i++)
#pragma unroll
        for (int j = 0; j < 4; j++)
#pragma unroll
            for (int c = 0; c < 4; c++) acc[i][j][c] = 0.f;

    const int a_lrow = lane & 15;
    const int a_koff = (lane >> 4) * 4;
    const int b_lrow = lane & 15;

    float4 avA, avB, bvA, bvB;
    avA = *(const float4*)(ApA);
    avB = *(const float4*)(ApB);
    bvA = *(const float4*)(BpA);
    bvB = *(const float4*)(BpB);
    {
        uint h01, h23, l01, l23;
        split4(avA, h01, h23, l01, l23);
        *(uint2*)&As[0][0][am0][ak0 >> 1]      = make_uint2(h01, h23);
        *(uint2*)&As[0][1][am0][ak0 >> 1]      = make_uint2(l01, l23);
        split4(avB, h01, h23, l01, l23);
        *(uint2*)&As[0][0][am0 + 64][ak0 >> 1] = make_uint2(h01, h23);
        *(uint2*)&As[0][1][am0 + 64][ak0 >> 1] = make_uint2(l01, l23);
        split4(bvA, h01, h23, l01, l23);
        *(uint2*)&Bs[0][0][bk0][bn0 >> 1]      = make_uint2(h01, h23);
        *(uint2*)&Bs[0][1][bk0][bn0 >> 1]      = make_uint2(l01, l23);
        split4(bvB, h01, h23, l01, l23);
        *(uint2*)&Bs[0][0][bk0 + 8][bn0 >> 1]  = make_uint2(h01, h23);
        *(uint2*)&Bs[0][1][bk0 + 8][bn0 >> 1]  = make_uint2(l01, l23);
    }
    __syncthreads();

    const int nk = K >> 4;
    for (int kt = 0; kt < nk; kt++) {
        const int buf = kt & 1;
        if (kt + 1 < nk) {
            const int ko = (kt + 1) << 4;
            avA = *(const float4*)(ApA + ko);
            avB = *(const float4*)(ApB + ko);
            bvA = *(const float4*)(BpA + (size_t)ko * N);
            bvB = *(const float4*)(BpB + (size_t)ko * N);
        }

        uint Ah[4][4], Al[4][4], Bh[4][2], Bl[4][2];
#pragma unroll
        for (int mt = 0; mt < 4; mt++) {
            int row = wm * 64 + mt * 16 + a_lrow;
            ldsm_x4(Ah[mt][0], Ah[mt][1], Ah[mt][2], Ah[mt][3],
                    &As[buf][0][row][a_koff]);
            ldsm_x4(Al[mt][0], Al[mt][1], Al[mt][2], Al[mt][3],
                    &As[buf][1][row][a_koff]);
        }
#pragma unroll
        for (int nt = 0; nt < 4; nt++) {
            int nu = wn * 16 + nt * 4;
            ldsm_x2t(Bh[nt][0], Bh[nt][1], &Bs[buf][0][b_lrow][nu]);
            ldsm_x2t(Bl[nt][0], Bl[nt][1], &Bs[buf][1][b_lrow][nu]);
        }

#pragma unroll
        for (int mt = 0; mt < 4; mt++) {
#pragma unroll
            for (int nt = 0; nt < 4; nt++) {
                mma_bf16(acc[mt][nt], Ah[mt][0], Ah[mt][1], Ah[mt][2], Ah[mt][3],
                         Bh[nt][0], Bh[nt][1]);
                mma_bf16(acc[mt][nt], Ah[mt][0], Ah[mt][1], Ah[mt][2], Ah[mt][3],
                         Bl[nt][0], Bl[nt][1]);
                mma_bf16(acc[mt][nt], Al[mt][0], Al[mt][1], Al[mt][2], Al[mt][3],
                         Bh[nt][0], Bh[nt][1]);
            }
        }

        if (kt + 1 < nk) {
            const int nb = buf ^ 1;
            uint h01, h23, l01, l23;
            split4(avA, h01, h23, l01, l23);
            *(uint2*)&As[nb][0][am0][ak0 >> 1]      = make_uint2(h01, h23);
            *(uint2*)&As[nb][1][am0][ak0 >> 1]      = make_uint2(l01, l23);
            split4(avB, h01, h23, l01, l23);
            *(uint2*)&As[nb][0][am0 + 64][ak0 >> 1] = make_uint2(h01, h23);
            *(uint2*)&As[nb][1][am0 + 64][ak0 >> 1] = make_uint2(l01, l23);
            split4(bvA, h01, h23, l01, l23);
            *(uint2*)&Bs[nb][0][bk0][bn0 >> 1]      = make_uint2(h01, h23);
            *(uint2*)&Bs[nb][1][bk0][bn0 >> 1]      = make_uint2(l01, l23);
            split4(bvB, h01, h23, l01, l23);
            *(uint2*)&Bs[nb][0][bk0 + 8][bn0 >> 1]  = make_uint2(h01, h23);
            *(uint2*)&Bs[nb][1][bk0 + 8][bn0 >> 1]  = make_uint2(l01, l23);
            __syncthreads();
        }
    }

#pragma unroll
    for (int mt = 0; mt < 4; mt++) {
        int row0 = brow + wm * 64 + mt * 16 + gid;
#pragma unroll
        for (int nt = 0; nt < 4; nt++) {
            int col0 = bcol + wn * 32 + nt * 8 + 2 * tig;
            float c0 = acc[mt][nt][0], c1 = acc[mt][nt][1];
            float c2 = acc[mt][nt][2], c3 = acc[mt][nt][3];
            if (act == 1) {
                c0 *= sigmoidf_(c0); c1 *= sigmoidf_(c1);
                c2 *= sigmoidf_(c2); c3 *= sigmoidf_(c3);
            } else if (act == 2) {
                c0 = sigmoidf_(c0); c1 = sigmoidf_(c1);
                c2 = sigmoidf_(c2); c3 = sigmoidf_(c3);
            }
            *(float2*)(C + (size_t)row0 * N + col0)       = make_float2(c0, c1);
            *(float2*)(C + (size_t)(row0 + 8) * N + col0) = make_float2(c2, c3);
        }
    }
}

__global__ __launch_bounds__(256) void ab_kernel(
    const float* __restrict__ x,
    const float* __restrict__ Wa, const float* __restrict__ ba,
    const float* __restrict__ Wb, const float* __restrict__ bb)
{
    int row  = blockIdx.x * 8 + (threadIdx.x >> 5);
    int lane = threadIdx.x & 31;
    const float* xr = x + (size_t)row * DDIM;
    const float* W  = (lane < 16) ? Wa : Wb;
    int h = lane & 15;

    float s0 = 0.f, s1 = 0.f, s2 = 0.f, s3 = 0.f;
#pragma unroll 4
    for (int i = 0; i < DDIM; i += 4) {
        s0 = fmaf(xr[i + 0], W[(i + 0) * HDIM + h], s0);
        s1 = fmaf(xr[i + 1], W[(i + 1) * HDIM + h], s1);
        s2 = fmaf(xr[i + 2], W[(i + 2) * HDIM + h], s2);
        s3 = fmaf(xr[i + 3], W[(i + 3) * HDIM + h], s3);
    }
    float s = (s0 + s1) + (s2 + s3);
    if (lane < 16) {
        float sg = sigmoidf_(s + ba[h]);
        g_scratch[OF_A + (size_t)row * HDIM + h] = fminf(fmaxf(sg, 0.1f), 1.0f);
    } else {
        float sg = sigmoidf_(s + bb[h]);
        g_scratch[OF_B + (size_t)row * HDIM + h] = fminf(sg, 1.0f);
    }
}

__global__ __launch_bounds__(512) void conv_kernel(
    const float* __restrict__ qcw, const float* __restrict__ qcb,
    const float* __restrict__ kcw, const float* __restrict__ kcb,
    const float* __restrict__ vcw, const float* __restrict__ vcb)
{
    int which = blockIdx.y;
    const float* w;
    const float* bias;
    size_t pre_off, out_off;
    int do_norm;
    if (which == 0) { w = qcw; bias = qcb; pre_off = OF_Q; out_off = OF_QN; do_norm = 1; }
    else if (which == 1) { w = kcw; bias = kcb; pre_off = OF_K; out_off = OF_KN; do_norm = 1; }
    else { w = vcw; bias = vcb; pre_off = OF_V; out_off = OF_VN; do_norm = 0; }

    const float* pre = (const float*)g_scratch + pre_off;
    float*       out = g_scratch + out_off;

    int row  = blockIdx.x;
    int t    = row & (TDIM - 1);
    int lane = threadIdx.x & 31;
    int h    = threadIdx.x >> 5;
    int c0   = h * 64 + lane;
    int c1   = c0 + 32;

    const float* p = pre + (size_t)row * DDIM;
    float v0 = bias[c0], v1 = bias[c1];
#pragma unroll
    for (int kk = 0; kk < 4; kk++) {
        int dt = kk - 3;
        if (t + dt >= 0) {
            const float* pr = p + (ptrdiff_t)dt * DDIM;
            v0 = fmaf(w[c0 * 4 + kk], pr[c0], v0);
            v1 = fmaf(w[c1 * 4 + kk], pr[c1], v1);
        }
    }
    v0 *= sigmoidf_(v0);
    v1 *= sigmoidf_(v1);

    if (do_norm) {
        float ss = v0 * v0 + v1 * v1;
#pragma unroll
        for (int o = 16; o > 0; o >>= 1) ss += __shfl_xor_sync(0xffffffffu, ss, o);
        float inv = 1.f / fmaxf(sqrtf(ss), 1e-6f);
        v0 *= inv; v1 *= inv;
    }
    out[(size_t)row * DDIM + c0] = v0;
    out[(size_t)row * DDIM + c1] = v1;
}

__device__ __forceinline__ void rec_load2(
    float* sk, float* sq, float* sv, float* sa, float* sb,
    const float* __restrict__ Kn, const float* __restrict__ Q,
    const float* __restrict__ V,
    const float* __restrict__ Al, const float* __restrict__ Be,
    size_t base, size_t abase, int c0, int t0, int tid)
{
    int e   = tid >> 4;
    int vec = (tid & 15) << 2;
    size_t go = base + (size_t)(t0 + e) * DDIM + vec;
    *(float4*)(sk + e * 64 + vec) = *(const float4*)(Kn + go);
    *(float4*)(sq + e * 64 + vec) = *(const float4*)(Q + go);
    if (tid < 32) {
        int ev = tid >> 2;
        int vv = (tid & 3) << 2;
        *(float4*)(sv + ev * 16 + vv) =
            *(const float4*)(V + base + (size_t)(t0 + ev) * DDIM + c0 + vv);
    } else if (tid < 40) {
        int ea = tid - 32;
        sa[ea] = Al[abase + (size_t)(t0 + ea) * HDIM];
    } else if (tid < 48) {
        int eb = tid - 40;
        sb[eb] = Be[abase + (size_t)(t0 + eb) * HDIM];
    }
}

// 2-step lookahead delta-rule recurrence (round-8 proven config).
__global__ __launch_bounds__(128) void rec_kernel()
{
    const float* Q  = g_scratch + OF_QN;
    const float* Kn = g_scratch + OF_KN;
    const float* V  = g_scratch + OF_VN;
    const float* Al = g_scratch + OF_A;
    const float* Be = g_scratch + OF_B;
    float*       O  = g_scratch + OF_O;

    int blk = blockIdx.x;
    int bh  = blk >> 2;
    int cq  = blk & 3;
    int c0  = cq * 16;
    int b   = bh >> 4, h = bh & 15;
    const size_t base  = (size_t)b * TDIM * DDIM + (size_t)h * 64;
    const size_t abase = (size_t)b * TDIM * HDIM + h;

    int tid = threadIdx.x;
    int g   = tid & 7;
    int jl  = tid >> 3;
    int j   = c0 + jl;
    int r0  = g * 8;

    __shared__ __align__(16) float sk[2][STAGE * 64];
    __shared__ __align__(16) float sq[2][STAGE * 64];
    __shared__ __align__(16) float sv[2][STAGE * 16];
    __shared__ float sa[2][STAGE];
    __shared__ float sb[2][STAGE];

    ull S2[4];
#pragma unroll
    for (int c = 0; c < 4; c++) S2[c] = 0ull;

    rec_load2(sk[0], sq[0], sv[0], sa[0], sb[0], Kn, Q, V, Al, Be,
              base, abase, c0, 0, tid);
    __syncthreads();

    const int nstages = TDIM / STAGE;
    for (int s = 0; s < nstages; s++) {
        const int buf = s & 1;
        if (s + 1 < nstages) {
            rec_load2(sk[buf ^ 1], sq[buf ^ 1], sv[buf ^ 1], sa[buf ^ 1], sb[buf ^ 1],
                      Kn, Q, V, Al, Be, base, abase, c0, (s + 1) * STAGE, tid);
        }
        const float* kbuf = sk[buf];
        const float* qbuf = sq[buf];
        const float* vbuf = sv[buf];

#pragma unroll
        for (int e = 0; e < STAGE; e += 2) {
            ull k0[4], k1[4], q0[4], q1[4];
            {
                const float* kp0 = kbuf + e * 64 + r0;
                const float* kp1 = kbuf + (e + 1) * 64 + r0;
                const float* qp0 = qbuf + e * 64 + r0;
                const float* qp1 = qbuf + (e + 1) * 64 + r0;
                *(ulonglong2*)(k0)     = *(const ulonglong2*)(kp0);
                *(ulonglong2*)(k0 + 2) = *(const ulonglong2*)(kp0 + 4);
                *(ulonglong2*)(k1)     = *(const ulonglong2*)(kp1);
                *(ulonglong2*)(k1 + 2) = *(const ulonglong2*)(kp1 + 4);
                *(ulonglong2*)(q0)     = *(const ulonglong2*)(qp0);
                *(ulonglong2*)(q0 + 2) = *(const ulonglong2*)(qp0 + 4);
                *(ulonglong2*)(q1)     = *(const ulonglong2*)(qp1);
                *(ulonglong2*)(q1 + 2) = *(const ulonglong2*)(qp1 + 4);
            }

            ull au0 = 0, ax1 = 0, aw0 = 0, ay1 = 0;
            ull akk = 0, ap00 = 0, ap01 = 0, ap11 = 0;
#pragma unroll
            for (int c = 0; c < 4; c++) {
                au0  = fma2_(S2[c], k0[c], au0);
                ax1  = fma2_(S2[c], k1[c], ax1);
                aw0  = fma2_(S2[c], q0[c], aw0);
                ay1  = fma2_(S2[c], q1[c], ay1);
                akk  = fma2_(k0[c], k1[c], akk);
                ap00 = fma2_(k0[c], q0[c], ap00);
                ap01 = fma2_(k0[c], q1[c], ap01);
                ap11 = fma2_(k1[c], q1[c], ap11);
            }
            float u0  = hadd2_(au0),  x1  = hadd2_(ax1);
            float w0  = hadd2_(aw0),  y1  = hadd2_(ay1);
            float kk  = hadd2_(akk),  p00 = hadd2_(ap00);
            float p01 = hadd2_(ap01), p11 = hadd2_(ap11);

#pragma unroll
            for (int off = 1; off <= 4; off <<= 1) {
                u0  += __shfl_xor_sync(0xffffffffu, u0,  off);
                x1  += __shfl_xor_sync(0xffffffffu, x1,  off);
                w0  += __shfl_xor_sync(0xffffffffu, w0,  off);
                y1  += __shfl_xor_sync(0xffffffffu, y1,  off);
                kk  += __shfl_xor_sync(0xffffffffu, kk,  off);
                p00 += __shfl_xor_sync(0xffffffffu, p00, off);
                p01 += __shfl_xor_sync(0xffffffffu, p01, off);
                p11 += __shfl_xor_sync(0xffffffffu, p11, off);
            }

            float a0 = sa[buf][e],     b0 = sb[buf][e];
            float a1 = sa[buf][e + 1], b1 = sb[buf][e + 1];
            float v0 = vbuf[e * 16 + jl];
            float v1 = vbuf[(e + 1) * 16 + jl];

            float bee0 = b0 * (v0 - u0);
            float o0   = fmaf(a0, w0, bee0 * p00);
            float u1   = fmaf(a0, x1, bee0 * kk);
            float bee1 = b1 * (v1 - u1);
            float w1   = fmaf(a0, y1, bee0 * p01);
            float o1   = fmaf(a1, w1, bee1 * p11);

            ull c01 = pack2_(a0 * a1);
            ull c0k = pack2_(a1 * bee0);
            ull c1k = pack2_(bee1);
#pragma unroll
            for (int c = 0; c < 4; c++)
                S2[c] = fma2_(c01, S2[c], fma2_(c0k, k0[c], mul2_(c1k, k1[c])));

            if (g == 0) {
                size_t oo = base + (size_t)(s * STAGE + e) * DDIM + j;
                O[oo]        = o0;
                O[oo + DDIM] = o1;
            }
        }
        __syncthreads();
    }
}

__global__ __launch_bounds__(512) void post_kernel(const float* __restrict__ rms_w)
{
    const float* O  = g_scratch + OF_O;
    const float* G  = g_scratch + OF_G;
    float*       Og = g_scratch + OF_OG;

    int row  = blockIdx.x;
    int lane = threadIdx.x & 31;
    int h    = threadIdx.x >> 5;
    size_t i0 = (size_t)row * DDIM + h * 64 + lane;

    float v0 = O[i0], v1 = O[i0 + 32];
    float ss = v0 * v0 + v1 * v1;
#pragma unroll
    for (int o = 16; o > 0; o >>= 1) ss += __shfl_xor_sync(0xffffffffu, ss, o);
    float inv = rsqrtf(ss * (1.f / 64.f) + 1e-6f);

    v0 = v0 * inv * rms_w[h * 64 + lane]      * G[i0];
    v1 = v1 * inv * rms_w[h * 64 + lane + 32] * G[i0 + 32];
    Og[i0]      = v0;
    Og[i0 + 32] = v1;
}

extern "C" void kernel_launch(void* const* d_in, const int* in_sizes, int n_in,
                              void* d_out, int out_size)
{
    (void)in_sizes; (void)n_in; (void)out_size;
    const float* x   = (const float*)d_in[0];
    const float* Wq  = (const float*)d_in[1];
    const float* Wk  = (const float*)d_in[2];
    const float* Wv  = (const float*)d_in[3];
    const float* Wo  = (const float*)d_in[4];
    const float* Wa  = (const float*)d_in[5];
    const float* ba  = (const float*)d_in[6];
    const float* Wb  = (const float*)d_in[7];
    const float* bb  = (const float*)d_in[8];
    const float* Wgd = (const float*)d_in[9];
    const float* Wgu = (const float*)d_in[10];
    const float* rms = (const float*)d_in[11];
    const float* qcw = (const float*)d_in[12];
    const float* qcb = (const float*)d_in[13];
    const float* kcw = (const float*)d_in[14];
    const float* kcb = (const float*)d_in[15];
    const float* vcw = (const float*)d_in[16];
    const float* vcb = (const float*)d_in[17];
    float* out = (float*)d_out;

    // 1) fused Q/K/V projection (3x8 = 24 column-block groups)
    {
        dim3 gqkv(24, MROWS / 128);
        gemm_tc<<<gqkv, 256>>>(x, 0, Wq, Wk, Wv, nullptr, OF_Q, 8,
                               MROWS, 1024, 1024, 0);
    }
    // 2) conv (q/k/v fused)
    {
        dim3 gc(MROWS, 3);
        conv_kernel<<<gc, 512>>>(qcw, qcb, kcw, kcb, vcw, vcb);
    }
    // 3) alpha/beta gates
    ab_kernel<<<MROWS / 8, 256>>>(x, Wa, ba, Wb, bb);
    // 4) recurrence  <-- ncu capture slot
    rec_kernel<<<BDIM * HDIM * 4, 128>>>();
    // 5-6) gate MLP
    {
        dim3 g512g(4, MROWS / 128);
        gemm_tc<<<g512g, 256>>>(x, 0, Wgd, Wgd, Wgd, nullptr, OF_XG, 4,
                                MROWS, 512, 1024, 1);
    }
    {
        dim3 g1024g(8, MROWS / 128);
        gemm_tc<<<g1024g, 256>>>(nullptr, OF_XG, Wgu, Wgu, Wgu, nullptr, OF_G, 8,
                                 MROWS, 1024, 512, 2);
    }
    // 7) RMSNorm + gate
    post_kernel<<<MROWS, 512>>>(rms);
    // 8) output projection
    {
        dim3 g1024g(8, MROWS / 128);
        gemm_tc<<<g1024g, 256>>>(nullptr, OF_OG, Wo, Wo, Wo, out, 0, 8,
                                 MROWS, 1024, 1024, 0);
    }
}

// round 12
// speedup vs baseline: 1.4224x; 1.1988x over previous
#include <cuda_runtime.h>
#include <cuda_bf16.h>

// ---------------------------------------------------------------------------
// GatedDeltaNet (B=2,T=4096,D=1024,H=16,DK=DV=64,KS=4)
// Round 12: CHUNKED delta rule (C=64). prep_kernel (parallel, 2048 CTAs)
// builds W,Uv,P,AQ,GkT per chunk via forward substitution; scan_kernel
// (128 CTAs) does the 64-step chunk scan with dense 64x64x16 matmuls.
// GEMMs/conv/ab/post unchanged from round 11 (best).
// ---------------------------------------------------------------------------

#define TDIM 4096
#define BDIM 2
#define HDIM 16
#define DDIM 1024
#define MROWS (BDIM * TDIM)
#define NCHUNK 64
#define NCH_TOT (BDIM * HDIM * NCHUNK)   // 2048

typedef unsigned long long ull;
typedef unsigned int uint;

static constexpr size_t NM   = (size_t)MROWS * DDIM;
static constexpr size_t OF_Q  = 0;
static constexpr size_t OF_K  = 1 * NM;
static constexpr size_t OF_V  = 2 * NM;
static constexpr size_t OF_QN = 3 * NM;
static constexpr size_t OF_KN = 4 * NM;
static constexpr size_t OF_VN = 5 * NM;
static constexpr size_t OF_G  = 6 * NM;
static constexpr size_t OF_O  = 7 * NM;
static constexpr size_t OF_OG = 8 * NM;
static constexpr size_t OF_XG = 9 * NM;
static constexpr size_t OF_A  = OF_XG + (size_t)MROWS * 512;
static constexpr size_t OF_B  = OF_A + (size_t)MROWS * HDIM;
static constexpr size_t CHMAT = (size_t)NCH_TOT * 4096;
static constexpr size_t OF_PG  = OF_B + (size_t)MROWS * HDIM;
static constexpr size_t OF_AQG = OF_PG + CHMAT;
static constexpr size_t OF_GKT = OF_AQG + CHMAT;
static constexpr size_t OF_WTG = OF_GKT + CHMAT;
static constexpr size_t OF_UVT = OF_WTG + CHMAT;
static constexpr size_t OF_ACG = OF_UVT + CHMAT;
static constexpr size_t SCRATCH_FLOATS = OF_ACG + NCH_TOT;

__device__ float g_scratch[SCRATCH_FLOATS];

__device__ __forceinline__ float sigmoidf_(float x) {
    return 1.f / (1.f + __expf(-x));
}
__device__ __forceinline__ ull fma2_(ull a, ull b, ull c) {
    ull d;
    asm("fma.rn.f32x2 %0, %1, %2, %3;" : "=l"(d) : "l"(a), "l"(b), "l"(c));
    return d;
}
__device__ __forceinline__ float hadd2_(ull a) {
    unsigned lo, hi;
    asm("mov.b64 {%0, %1}, %2;" : "=r"(lo), "=r"(hi) : "l"(a));
    return __uint_as_float(lo) + __uint_as_float(hi);
}
__device__ __forceinline__ void mma_bf16(float c[4],
    uint a0, uint a1, uint a2, uint a3, uint b0, uint b1)
{
    asm volatile(
        "mma.sync.aligned.m16n8k16.row.col.f32.bf16.bf16.f32 "
        "{%0,%1,%2,%3},{%4,%5,%6,%7},{%8,%9},{%0,%1,%2,%3};"
        : "+f"(c[0]), "+f"(c[1]), "+f"(c[2]), "+f"(c[3])
        : "r"(a0), "r"(a1), "r"(a2), "r"(a3), "r"(b0), "r"(b1));
}
__device__ __forceinline__ void ldsm_x4(uint& r0, uint& r1, uint& r2, uint& r3,
                                        const void* p)
{
    uint a = (uint)__cvta_generic_to_shared(p);
    asm volatile("ldmatrix.sync.aligned.m8n8.x4.shared.b16 {%0,%1,%2,%3},[%4];"
                 : "=r"(r0), "=r"(r1), "=r"(r2), "=r"(r3) : "r"(a));
}
__device__ __forceinline__ void ldsm_x2t(uint& r0, uint& r1, const void* p)
{
    uint a = (uint)__cvta_generic_to_shared(p);
    asm volatile("ldmatrix.sync.aligned.m8n8.x2.trans.shared.b16 {%0,%1},[%2];"
                 : "=r"(r0), "=r"(r1) : "r"(a));
}
__device__ __forceinline__ void split4(float4 v, uint& h01, uint& h23,
                                       uint& l01, uint& l23)
{
    __nv_bfloat162 h01b = __floats2bfloat162_rn(v.x, v.y);
    __nv_bfloat162 h23b = __floats2bfloat162_rn(v.z, v.w);
    float r0 = v.x - __bfloat162float(h01b.x);
    float r1 = v.y - __bfloat162float(h01b.y);
    float r2 = v.z - __bfloat162float(h23b.x);
    float r3 = v.w - __bfloat162float(h23b.y);
    __nv_bfloat162 l01b = __floats2bfloat162_rn(r0, r1);
    __nv_bfloat162 l23b = __floats2bfloat162_rn(r2, r3);
    h01 = *(uint*)&h01b;  h23 = *(uint*)&h23b;
    l01 = *(uint*)&l01b;  l23 = *(uint*)&l23b;
}

#define A_STRIDE 12
#define B_STRIDE 68

__global__ __launch_bounds__(256) void gemm_tc(
    const float* __restrict__ Aext, size_t Aoff,
    const float* __restrict__ W0, const float* __restrict__ W1,
    const float* __restrict__ W2,
    float* __restrict__ Cext, size_t Coff, int nblk,
    int M, int N, int K, int act)
{
    const float* A = Aext ? Aext : (const float*)g_scratch + Aoff;
    const int which = blockIdx.x / nblk;
    const float* W = (which == 0) ? W0 : (which == 1) ? W1 : W2;
    float* C = Cext ? Cext : g_scratch + Coff + (size_t)which * NM;

    __shared__ __align__(16) uint As[2][2][128][A_STRIDE];
    __shared__ __align__(16) uint Bs[2][2][16][B_STRIDE];

    const int tid  = threadIdx.x;
    const int brow = blockIdx.y * 128;
    const int bcol = (blockIdx.x % nblk) * 128;
    const int lane = tid & 31;
    const int warp = tid >> 5;
    const int wm   = warp >> 2;
    const int wn   = warp & 3;
    const int gid  = lane >> 2;
    const int tig  = lane & 3;
    const int am0 = tid >> 2;
    const int ak0 = (tid & 3) << 2;
    const int bk0 = tid >> 5;
    const int bn0 = (tid & 31) << 2;

    const float* ApA = A + (size_t)(brow + am0) * K + ak0;
    const float* ApB = ApA + (size_t)64 * K;
    const float* BpA = W + (size_t)bk0 * N + bcol + bn0;
    const float* BpB = BpA + (size_t)8 * N;

    float acc[4][4][4];
#pragma unroll
    for (int i = 0; i < 4; i++)
#pragma unroll
        for (int j = 0; j < 4; j++)
#pragma unroll
            for (int c = 0; c < 4; c++) acc[i][j][c] = 0.f;

    const int a_lrow = lane & 15;
    const int a_koff = (lane >> 4) * 4;
    const int b_lrow = lane & 15;

    float4 avA, avB, bvA, bvB;
    avA = *(const float4*)(ApA);
    avB = *(const float4*)(ApB);
    bvA = *(const float4*)(BpA);
    bvB = *(const float4*)(BpB);
    {
        uint h01, h23, l01, l23;
        split4(avA, h01, h23, l01, l23);
        *(uint2*)&As[0][0][am0][ak0 >> 1]      = make_uint2(h01, h23);
        *(uint2*)&As[0][1][am0][ak0 >> 1]      = make_uint2(l01, l23);
        split4(avB, h01, h23, l01, l23);
        *(uint2*)&As[0][0][am0 + 64][ak0 >> 1] = make_uint2(h01, h23);
        *(uint2*)&As[0][1][am0 + 64][ak0 >> 1] = make_uint2(l01, l23);
        split4(bvA, h01, h23, l01, l23);
        *(uint2*)&Bs[0][0][bk0][bn0 >> 1]      = make_uint2(h01, h23);
        *(uint2*)&Bs[0][1][bk0][bn0 >> 1]      = make_uint2(l01, l23);
        split4(bvB, h01, h23, l01, l23);
        *(uint2*)&Bs[0][0][bk0 + 8][bn0 >> 1]  = make_uint2(h01, h23);
        *(uint2*)&Bs[0][1][bk0 + 8][bn0 >> 1]  = make_uint2(l01, l23);
    }
    __syncthreads();

    const int nk = K >> 4;
    for (int kt = 0; kt < nk; kt++) {
        const int buf = kt & 1;
        if (kt + 1 < nk) {
            const int ko = (kt + 1) << 4;
            avA = *(const float4*)(ApA + ko);
            avB = *(const float4*)(ApB + ko);
            bvA = *(const float4*)(BpA + (size_t)ko * N);
            bvB = *(const float4*)(BpB + (size_t)ko * N);
        }
        uint Ah[4][4], Al[4][4], Bh[4][2], Bl[4][2];
#pragma unroll
        for (int mt = 0; mt < 4; mt++) {
            int row = wm * 64 + mt * 16 + a_lrow;
            ldsm_x4(Ah[mt][0], Ah[mt][1], Ah[mt][2], Ah[mt][3],
                    &As[buf][0][row][a_koff]);
            ldsm_x4(Al[mt][0], Al[mt][1], Al[mt][2], Al[mt][3],
                    &As[buf][1][row][a_koff]);
        }
#pragma unroll
        for (int nt = 0; nt < 4; nt++) {
            int nu = wn * 16 + nt * 4;
            ldsm_x2t(Bh[nt][0], Bh[nt][1], &Bs[buf][0][b_lrow][nu]);
            ldsm_x2t(Bl[nt][0], Bl[nt][1], &Bs[buf][1][b_lrow][nu]);
        }
#pragma unroll
        for (int mt = 0; mt < 4; mt++) {
#pragma unroll
            for (int nt = 0; nt < 4; nt++) {
                mma_bf16(acc[mt][nt], Ah[mt][0], Ah[mt][1], Ah[mt][2], Ah[mt][3],
                         Bh[nt][0], Bh[nt][1]);
                mma_bf16(acc[mt][nt], Ah[mt][0], Ah[mt][1], Ah[mt][2], Ah[mt][3],
                         Bl[nt][0], Bl[nt][1]);
                mma_bf16(acc[mt][nt], Al[mt][0], Al[mt][1], Al[mt][2], Al[mt][3],
                         Bh[nt][0], Bh[nt][1]);
            }
        }
        if (kt + 1 < nk) {
            const int nb = buf ^ 1;
            uint h01, h23, l01, l23;
            split4(avA, h01, h23, l01, l23);
            *(uint2*)&As[nb][0][am0][ak0 >> 1]      = make_uint2(h01, h23);
            *(uint2*)&As[nb][1][am0][ak0 >> 1]      = make_uint2(l01, l23);
            split4(avB, h01, h23, l01, l23);
            *(uint2*)&As[nb][0][am0 + 64][ak0 >> 1] = make_uint2(h01, h23);
            *(uint2*)&As[nb][1][am0 + 64][ak0 >> 1] = make_uint2(l01, l23);
            split4(bvA, h01, h23, l01, l23);
            *(uint2*)&Bs[nb][0][bk0][bn0 >> 1]      = make_uint2(h01, h23);
            *(uint2*)&Bs[nb][1][bk0][bn0 >> 1]      = make_uint2(l01, l23);
            split4(bvB, h01, h23, l01, l23);
            *(uint2*)&Bs[nb][0][bk0 + 8][bn0 >> 1]  = make_uint2(h01, h23);
            *(uint2*)&Bs[nb][1][bk0 + 8][bn0 >> 1]  = make_uint2(l01, l23);
            __syncthreads();
        }
    }
#pragma unroll
    for (int mt = 0; mt < 4; mt++) {
        int row0 = brow + wm * 64 + mt * 16 + gid;
#pragma unroll
        for (int nt = 0; nt < 4; nt++) {
            int col0 = bcol + wn * 32 + nt * 8 + 2 * tig;
            float c0 = acc[mt][nt][0], c1 = acc[mt][nt][1];
            float c2 = acc[mt][nt][2], c3 = acc[mt][nt][3];
            if (act == 1) {
                c0 *= sigmoidf_(c0); c1 *= sigmoidf_(c1);
                c2 *= sigmoidf_(c2); c3 *= sigmoidf_(c3);
            } else if (act == 2) {
                c0 = sigmoidf_(c0); c1 = sigmoidf_(c1);
                c2 = sigmoidf_(c2); c3 = sigmoidf_(c3);
            }
            *(float2*)(C + (size_t)row0 * N + col0)       = make_float2(c0, c1);
            *(float2*)(C + (size_t)(row0 + 8) * N + col0) = make_float2(c2, c3);
        }
    }
}

__global__ __launch_bounds__(256) void ab_kernel(
    const float* __restrict__ x,
    const float* __restrict__ Wa, const float* __restrict__ ba,
    const float* __restrict__ Wb, const float* __restrict__ bb)
{
    int row  = blockIdx.x * 8 + (threadIdx.x >> 5);
    int lane = threadIdx.x & 31;
    const float* xr = x + (size_t)row * DDIM;
    const float* W  = (lane < 16) ? Wa : Wb;
    int h = lane & 15;
    float s0 = 0.f, s1 = 0.f, s2 = 0.f, s3 = 0.f;
#pragma unroll 4
    for (int i = 0; i < DDIM; i += 4) {
        s0 = fmaf(xr[i + 0], W[(i + 0) * HDIM + h], s0);
        s1 = fmaf(xr[i + 1], W[(i + 1) * HDIM + h], s1);
        s2 = fmaf(xr[i + 2], W[(i + 2) * HDIM + h], s2);
        s3 = fmaf(xr[i + 3], W[(i + 3) * HDIM + h], s3);
    }
    float s = (s0 + s1) + (s2 + s3);
    if (lane < 16) {
        float sg = sigmoidf_(s + ba[h]);
        g_scratch[OF_A + (size_t)row * HDIM + h] = fminf(fmaxf(sg, 0.1f), 1.0f);
    } else {
        float sg = sigmoidf_(s + bb[h]);
        g_scratch[OF_B + (size_t)row * HDIM + h] = fminf(sg, 1.0f);
    }
}

__global__ __launch_bounds__(512) void conv_kernel(
    const float* __restrict__ qcw, const float* __restrict__ qcb,
    const float* __restrict__ kcw, const float* __restrict__ kcb,
    const float* __restrict__ vcw, const float* __restrict__ vcb)
{
    int which = blockIdx.y;
    const float* w;
    const float* bias;
    size_t pre_off, out_off;
    int do_norm;
    if (which == 0) { w = qcw; bias = qcb; pre_off = OF_Q; out_off = OF_QN; do_norm = 1; }
    else if (which == 1) { w = kcw; bias = kcb; pre_off = OF_K; out_off = OF_KN; do_norm = 1; }
    else { w = vcw; bias = vcb; pre_off = OF_V; out_off = OF_VN; do_norm = 0; }

    const float* pre = (const float*)g_scratch + pre_off;
    float*       out = g_scratch + out_off;
    int row  = blockIdx.x;
    int t    = row & (TDIM - 1);
    int lane = threadIdx.x & 31;
    int h    = threadIdx.x >> 5;
    int c0   = h * 64 + lane;
    int c1   = c0 + 32;

    const float* p = pre + (size_t)row * DDIM;
    float v0 = bias[c0], v1 = bias[c1];
#pragma unroll
    for (int kk = 0; kk < 4; kk++) {
        int dt = kk - 3;
        if (t + dt >= 0) {
            const float* pr = p + (ptrdiff_t)dt * DDIM;
            v0 = fmaf(w[c0 * 4 + kk], pr[c0], v0);
            v1 = fmaf(w[c1 * 4 + kk], pr[c1], v1);
        }
    }
    v0 *= sigmoidf_(v0);
    v1 *= sigmoidf_(v1);
    if (do_norm) {
        float ss = v0 * v0 + v1 * v1;
#pragma unroll
        for (int o = 16; o > 0; o >>= 1) ss += __shfl_xor_sync(0xffffffffu, ss, o);
        float inv = 1.f / fmaxf(sqrtf(ss), 1e-6f);
        v0 *= inv; v1 *= inv;
    }
    out[(size_t)row * DDIM + c0] = v0;
    out[(size_t)row * DDIM + c1] = v1;
}

// ---------------------------------------------------------------------------
// prep_kernel: one CTA per chunk (2048 CTAs, 256 threads).
// Builds P, AQ, GkT, then solves (I+M)[Uv|W] = [b*V | b*Aprev*K] by forward
// substitution, writes UvT and W. Decay ratios in log2 space (no underflow).
// ---------------------------------------------------------------------------
__global__ __launch_bounds__(256) void prep_kernel()
{
    extern __shared__ float sm[];
    float* Kc  = sm;                 // [64][68]
    float* Qv  = sm + 4352;          // [64][68]  Q then V
    float* MM  = sm + 8704;          // [64][68]
    float* XX  = sm + 13056;         // [64][132]
    float* sLc = sm + 21504;         // inclusive cumsum log2(a)
    float* sLp = sm + 21568;         // exclusive
    float* sbv = sm + 21632;         // beta

    const float* Qn = g_scratch + OF_QN;
    const float* Kn = g_scratch + OF_KN;
    const float* Vn = g_scratch + OF_VN;
    const float* Al = g_scratch + OF_A;
    const float* Be = g_scratch + OF_B;

    int cid = blockIdx.x;
    int bh = cid >> 6, ci = cid & 63;
    int b = bh >> 4, h = bh & 15;
    int t0 = ci << 6;
    size_t base  = (size_t)b * TDIM * DDIM + (size_t)h * 64 + (size_t)t0 * DDIM;
    size_t abase = (size_t)b * TDIM * HDIM + h + (size_t)t0 * HDIM;
    int tid = threadIdx.x;

    if (tid < 64) {
        sLc[tid] = log2f(Al[abase + (size_t)tid * HDIM]);
        sbv[tid] = Be[abase + (size_t)tid * HDIM];
    }
    __syncthreads();
    if (tid == 0) {
        float run = 0.f;
        for (int i = 0; i < 64; i++) { sLp[i] = run; run += sLc[i]; sLc[i] = run; }
    }
    // load K, Q
    {
        int row = tid >> 4;
        int col = (tid & 15) << 2;
        for (int rr = 0; rr < 4; rr++) {
            int r = row + rr * 16;
            *(float4*)&Kc[r * 68 + col] = *(const float4*)(Kn + base + (size_t)r * DDIM + col);
            *(float4*)&Qv[r * 68 + col] = *(const float4*)(Qn + base + (size_t)r * DDIM + col);
        }
    }
    __syncthreads();

    float* Pg  = g_scratch + OF_PG  + (size_t)cid * 4096;
    float* AQg = g_scratch + OF_AQG + (size_t)cid * 4096;
    float* Gg  = g_scratch + OF_GKT + (size_t)cid * 4096;
    float* Wg  = g_scratch + OF_WTG + (size_t)cid * 4096;
    float* Ug  = g_scratch + OF_UVT + (size_t)cid * 4096;

    float Lc63 = sLc[63];
    // P[t][i] (i<=t), AQ[t][k], GkT[r][i]
    for (int kq = 0; kq < 16; kq++) {
        int e = kq * 256 + tid;
        int t = e >> 6, i = e & 63;
        float pv = 0.f;
        if (i <= t) {
            ull a0 = 0, a1 = 0;
#pragma unroll 8
            for (int m = 0; m < 64; m += 4) {
                a0 = fma2_(*(ull*)&Qv[t * 68 + m],     *(ull*)&Kc[i * 68 + m],     a0);
                a1 = fma2_(*(ull*)&Qv[t * 68 + m + 2], *(ull*)&Kc[i * 68 + m + 2], a1);
            }
            pv = exp2f(sLc[t] - sLc[i]) * (hadd2_(a0) + hadd2_(a1));
        }
        Pg[e]  = pv;
        AQg[e] = exp2f(sLc[t]) * Qv[t * 68 + i];
        Gg[e]  = exp2f(Lc63 - sLc[i]) * Kc[i * 68 + t];
    }
    __syncthreads();
    // load V into Qv
    {
        int row = tid >> 4;
        int col = (tid & 15) << 2;
        for (int rr = 0; rr < 4; rr++) {
            int r = row + rr * 16;
            *(float4*)&Qv[r * 68 + col] = *(const float4*)(Vn + base + (size_t)r * DDIM + col);
        }
    }
    __syncthreads();
    // MM (strictly lower)
    for (int kq = 0; kq < 16; kq++) {
        int e = kq * 256 + tid;
        int i = e >> 6, j = e & 63;
        if (j < i) {
            ull a0 = 0, a1 = 0;
#pragma unroll 8
            for (int m = 0; m < 64; m += 4) {
                a0 = fma2_(*(ull*)&Kc[i * 68 + m],     *(ull*)&Kc[j * 68 + m],     a0);
                a1 = fma2_(*(ull*)&Kc[i * 68 + m + 2], *(ull*)&Kc[j * 68 + m + 2], a1);
            }
            MM[i * 68 + j] = sbv[i] * exp2f(sLp[i] - sLc[j]) * (hadd2_(a0) + hadd2_(a1));
        }
    }
    // RHS: cols 0..63 = b*V, cols 64..127 = b*Aprev*K
    for (int kq = 0; kq < 32; kq++) {
        int e = kq * 256 + tid;
        int i = e >> 7, c = e & 127;
        if (c < 64) XX[i * 132 + c] = sbv[i] * Qv[i * 68 + c];
        else        XX[i * 132 + c] = sbv[i] * exp2f(sLp[i]) * Kc[i * 68 + (c - 64)];
    }
    __syncthreads();
    // forward substitution: each thread owns one of 128 RHS columns
    if (tid < 128) {
        int c = tid;
        for (int i = 1; i < 64; i++) {
            float a0 = 0.f, a1 = 0.f;
            int j = 0;
            for (; j + 1 < i; j += 2) {
                a0 = fmaf(MM[i * 68 + j],     XX[j * 132 + c],       a0);
                a1 = fmaf(MM[i * 68 + j + 1], XX[(j + 1) * 132 + c], a1);
            }
            if (j < i) a0 = fmaf(MM[i * 68 + j], XX[j * 132 + c], a0);
            XX[i * 132 + c] -= (a0 + a1);
        }
    }
    __syncthreads();
    // write UvT[c][i] and W[i][k]
    for (int kq = 0; kq < 16; kq++) {
        int e = kq * 256 + tid;
        { int c = e >> 6, i = e & 63; Ug[e] = XX[i * 132 + c]; }
        { int i = e >> 6, kk = e & 63; Wg[e] = XX[i * 132 + 64 + kk]; }
    }
    if (tid == 0) g_scratch[OF_ACG + cid] = exp2f(Lc63);
}

// ---------------------------------------------------------------------------
// scan_kernel: 128 CTAs (bh*4 + col-quarter), 128 threads. Sequential over
// 64 chunks: U = Uv - W*S; O = AQ*S + P*U; S = AC*S + GkT*U.
// ---------------------------------------------------------------------------
__global__ __launch_bounds__(128) void scan_kernel()
{
    extern __shared__ float sm[];
    float* mW  = sm;            // [64][68]
    float* mAQ = sm + 4352;
    float* mP  = sm + 8704;
    float* mG  = sm + 13056;
    float* S_T = sm + 17408;    // [16][68]
    float* U_T = sm + 18496;    // [16][68]

    int blk = blockIdx.x;
    int bh = blk >> 2, cq = blk & 3;
    int c0 = cq << 4;
    int b = bh >> 4, h = bh & 15;
    size_t obase = (size_t)b * TDIM * DDIM + (size_t)h * 64;
    int tid = threadIdx.x;
    int cc = tid & 15, grp = tid >> 4;

    for (int e = tid; e < 16 * 68; e += 128) S_T[e] = 0.f;
    __syncthreads();

    float* O = g_scratch + OF_O;

    for (int ch = 0; ch < NCHUNK; ch++) {
        int cid = bh * 64 + ch;
        const float* Wg  = g_scratch + OF_WTG + (size_t)cid * 4096;
        const float* AQg = g_scratch + OF_AQG + (size_t)cid * 4096;
        const float* Pg  = g_scratch + OF_PG  + (size_t)cid * 4096;
        const float* Gg  = g_scratch + OF_GKT + (size_t)cid * 4096;
        const float* Ug  = g_scratch + OF_UVT + (size_t)cid * 4096;

        for (int kq = 0; kq < 8; kq++) {
            int e4 = kq * 128 + tid;
            int r = e4 >> 4, c4 = (e4 & 15) << 2;
            *(float4*)&mW[r * 68 + c4]  = *(const float4*)(Wg  + r * 64 + c4);
            *(float4*)&mAQ[r * 68 + c4] = *(const float4*)(AQg + r * 64 + c4);
            *(float4*)&mP[r * 68 + c4]  = *(const float4*)(Pg  + r * 64 + c4);
            *(float4*)&mG[r * 68 + c4]  = *(const float4*)(Gg  + r * 64 + c4);
        }
        for (int kq = 0; kq < 2; kq++) {
            int e4 = kq * 128 + tid;
            int r = e4 >> 4, c4 = (e4 & 15) << 2;
            *(float4*)&U_T[r * 68 + c4] = *(const float4*)(Ug + (size_t)(c0 + r) * 64 + c4);
        }
        float AC = g_scratch[OF_ACG + cid];
        __syncthreads();

        // phase U: U_T[cc][i] -= sum_k W[i][k]*S_T[cc][k]
        {
            ull aU[8][2];
#pragma unroll
            for (int ii = 0; ii < 8; ii++) { aU[ii][0] = 0; aU[ii][1] = 0; }
#pragma unroll
            for (int k4 = 0; k4 < 16; k4++) {
                ull s01 = *(ull*)&S_T[cc * 68 + k4 * 4];
                ull s23 = *(ull*)&S_T[cc * 68 + k4 * 4 + 2];
#pragma unroll
                for (int ii = 0; ii < 8; ii++) {
                    int i = grp * 8 + ii;
                    aU[ii][0] = fma2_(*(ull*)&mW[i * 68 + k4 * 4],     s01, aU[ii][0]);
                    aU[ii][1] = fma2_(*(ull*)&mW[i * 68 + k4 * 4 + 2], s23, aU[ii][1]);
                }
            }
#pragma unroll
            for (int ii = 0; ii < 8; ii++) {
                int i = grp * 8 + ii;
                U_T[cc * 68 + i] -= (hadd2_(aU[ii][0]) + hadd2_(aU[ii][1]));
            }
        }
        // phase O1: oacc[t] = sum_k AQ[t][k]*S_T[cc][k]
        float oacc[8];
        {
            ull aO[8][2];
#pragma unroll
            for (int ii = 0; ii < 8; ii++) { aO[ii][0] = 0; aO[ii][1] = 0; }
#pragma unroll
            for (int k4 = 0; k4 < 16; k4++) {
                ull s01 = *(ull*)&S_T[cc * 68 + k4 * 4];
                ull s23 = *(ull*)&S_T[cc * 68 + k4 * 4 + 2];
#pragma unroll
                for (int ii = 0; ii < 8; ii++) {
                    int t = grp * 8 + ii;
                    aO[ii][0] = fma2_(*(ull*)&mAQ[t * 68 + k4 * 4],     s01, aO[ii][0]);
                    aO[ii][1] = fma2_(*(ull*)&mAQ[t * 68 + k4 * 4 + 2], s23, aO[ii][1]);
                }
            }
#pragma unroll
            for (int ii = 0; ii < 8; ii++)
                oacc[ii] = hadd2_(aO[ii][0]) + hadd2_(aO[ii][1]);
        }
        __syncthreads();   // U_T complete
        // phase O2: oacc[t] += sum_i P[t][i]*U_T[cc][i]; write O
        {
            ull aO[8][2];
#pragma unroll
            for (int ii = 0; ii < 8; ii++) { aO[ii][0] = 0; aO[ii][1] = 0; }
#pragma unroll
            for (int k4 = 0; k4 < 16; k4++) {
                ull u01 = *(ull*)&U_T[cc * 68 + k4 * 4];
                ull u23 = *(ull*)&U_T[cc * 68 + k4 * 4 + 2];
#pragma unroll
                for (int ii = 0; ii < 8; ii++) {
                    int t = grp * 8 + ii;
                    aO[ii][0] = fma2_(*(ull*)&mP[t * 68 + k4 * 4],     u01, aO[ii][0]);
                    aO[ii][1] = fma2_(*(ull*)&mP[t * 68 + k4 * 4 + 2], u23, aO[ii][1]);
                }
            }
#pragma unroll
            for (int ii = 0; ii < 8; ii++) {
                int t = grp * 8 + ii;
                float ov = oacc[ii] + hadd2_(aO[ii][0]) + hadd2_(aO[ii][1]);
                O[obase + (size_t)(ch * 64 + t) * DDIM + c0 + cc] = ov;
            }
        }
        // phase S: S_T[cc][r] = AC*S_T[cc][r] + sum_i GkT[r][i]*U_T[cc][i]
        {
            ull aS[8][2];
#pragma unroll
            for (int ii = 0; ii < 8; ii++) { aS[ii][0] = 0; aS[ii][1] = 0; }
#pragma unroll
            for (int k4 = 0; k4 < 16; k4++) {
                ull u01 = *(ull*)&U_T[cc * 68 + k4 * 4];
                ull u23 = *(ull*)&U_T[cc * 68 + k4 * 4 + 2];
#pragma unroll
                for (int ii = 0; ii < 8; ii++) {
                    int r = grp * 8 + ii;
                    aS[ii][0] = fma2_(*(ull*)&mG[r * 68 + k4 * 4],     u01, aS[ii][0]);
                    aS[ii][1] = fma2_(*(ull*)&mG[r * 68 + k4 * 4 + 2], u23, aS[ii][1]);
                }
            }
#pragma unroll
            for (int ii = 0; ii < 8; ii++) {
                int r = grp * 8 + ii;
                S_T[cc * 68 + r] = AC * S_T[cc * 68 + r]
                                   + hadd2_(aS[ii][0]) + hadd2_(aS[ii][1]);
            }
        }
        __syncthreads();
    }
}

__global__ __launch_bounds__(512) void post_kernel(const float* __restrict__ rms_w)
{
    const float* O  = g_scratch + OF_O;
    const float* G  = g_scratch + OF_G;
    float*       Og = g_scratch + OF_OG;
    int row  = blockIdx.x;
    int lane = threadIdx.x & 31;
    int h    = threadIdx.x >> 5;
    size_t i0 = (size_t)row * DDIM + h * 64 + lane;
    float v0 = O[i0], v1 = O[i0 + 32];
    float ss = v0 * v0 + v1 * v1;
#pragma unroll
    for (int o = 16; o > 0; o >>= 1) ss += __shfl_xor_sync(0xffffffffu, ss, o);
    float inv = rsqrtf(ss * (1.f / 64.f) + 1e-6f);
    v0 = v0 * inv * rms_w[h * 64 + lane]      * G[i0];
    v1 = v1 * inv * rms_w[h * 64 + lane + 32] * G[i0 + 32];
    Og[i0]      = v0;
    Og[i0 + 32] = v1;
}

extern "C" void kernel_launch(void* const* d_in, const int* in_sizes, int n_in,
                              void* d_out, int out_size)
{
    (void)in_sizes; (void)n_in; (void)out_size;
    const float* x   = (const float*)d_in[0];
    const float* Wq  = (const float*)d_in[1];
    const float* Wk  = (const float*)d_in[2];
    const float* Wv  = (const float*)d_in[3];
    const float* Wo  = (const float*)d_in[4];
    const float* Wa  = (const float*)d_in[5];
    const float* ba  = (const float*)d_in[6];
    const float* Wb  = (const float*)d_in[7];
    const float* bb  = (const float*)d_in[8];
    const float* Wgd = (const float*)d_in[9];
    const float* Wgu = (const float*)d_in[10];
    const float* rms = (const float*)d_in[11];
    const float* qcw = (const float*)d_in[12];
    const float* qcb = (const float*)d_in[13];
    const float* kcw = (const float*)d_in[14];
    const float* kcb = (const float*)d_in[15];
    const float* vcw = (const float*)d_in[16];
    const float* vcb = (const float*)d_in[17];
    float* out = (float*)d_out;

    cudaFuncSetAttribute(prep_kernel, cudaFuncAttributeMaxDynamicSharedMemorySize, 90112);
    cudaFuncSetAttribute(scan_kernel, cudaFuncAttributeMaxDynamicSharedMemorySize, 81920);

    // 1) alpha/beta
    ab_kernel<<<MROWS / 8, 256>>>(x, Wa, ba, Wb, bb);
    // 2) fused QKV projection
    {
        dim3 gqkv(24, MROWS / 128);
        gemm_tc<<<gqkv, 256>>>(x, 0, Wq, Wk, Wv, nullptr, OF_Q, 8,
                               MROWS, 1024, 1024, 0);
    }
    // 3) conv
    {
        dim3 gc(MROWS, 3);
        conv_kernel<<<gc, 512>>>(qcw, qcb, kcw, kcb, vcw, vcb);
    }
    // 4) chunk prep (parallel)
    prep_kernel<<<NCH_TOT, 256, 90112>>>();
    // 5) chunk scan (sequential over chunks)
    scan_kernel<<<BDIM * HDIM * 4, 128, 81920>>>();
    // 6-7) gate MLP
    {
        dim3 g512g(4, MROWS / 128);
        gemm_tc<<<g512g, 256>>>(x, 0, Wgd, Wgd, Wgd, nullptr, OF_XG, 4,
                                MROWS, 512, 1024, 1);
    }
    {
        dim3 g1024g(8, MROWS / 128);
        gemm_tc<<<g1024g, 256>>>(nullptr, OF_XG, Wgu, Wgu, Wgu, nullptr, OF_G, 8,
                                 MROWS, 1024, 512, 2);
    }
    // 8) RMSNorm + gate
    post_kernel<<<MROWS, 512>>>(rms);
    // 9) output projection
    {
        dim3 g1024g(8, MROWS / 128);
        gemm_tc<<<g1024g, 256>>>(nullptr, OF_OG, Wo, Wo, Wo, out, 0, 8,
                                 MROWS, 1024, 1024, 0);
    }
}

// round 13
// speedup vs baseline: 1.5928x; 1.1198x over previous
#include <cuda_runtime.h>
#include <cuda_bf16.h>

// ---------------------------------------------------------------------------
// GatedDeltaNet (B=2,T=4096,D=1024,H=16,DK=DV=64,KS=4)
// Round 13: prep_kernel rewrite — register-resident forward substitution
// (fully unrolled, one column per thread), XX removed from smem (90KB->53KB,
// 4 CTAs/SM), b*exp2(Lp) precomputed. Rest identical to round-12 winner.
// ---------------------------------------------------------------------------

#define TDIM 4096
#define BDIM 2
#define HDIM 16
#define DDIM 1024
#define MROWS (BDIM * TDIM)
#define NCHUNK 64
#define NCH_TOT (BDIM * HDIM * NCHUNK)   // 2048

typedef unsigned long long ull;
typedef unsigned int uint;

static constexpr size_t NM   = (size_t)MROWS * DDIM;
static constexpr size_t OF_Q  = 0;
static constexpr size_t OF_K  = 1 * NM;
static constexpr size_t OF_V  = 2 * NM;
static constexpr size_t OF_QN = 3 * NM;
static constexpr size_t OF_KN = 4 * NM;
static constexpr size_t OF_VN = 5 * NM;
static constexpr size_t OF_G  = 6 * NM;
static constexpr size_t OF_O  = 7 * NM;
static constexpr size_t OF_OG = 8 * NM;
static constexpr size_t OF_XG = 9 * NM;
static constexpr size_t OF_A  = OF_XG + (size_t)MROWS * 512;
static constexpr size_t OF_B  = OF_A + (size_t)MROWS * HDIM;
static constexpr size_t CHMAT = (size_t)NCH_TOT * 4096;
static constexpr size_t OF_PG  = OF_B + (size_t)MROWS * HDIM;
static constexpr size_t OF_AQG = OF_PG + CHMAT;
static constexpr size_t OF_GKT = OF_AQG + CHMAT;
static constexpr size_t OF_WTG = OF_GKT + CHMAT;
static constexpr size_t OF_UVT = OF_WTG + CHMAT;
static constexpr size_t OF_ACG = OF_UVT + CHMAT;
static constexpr size_t SCRATCH_FLOATS = OF_ACG + NCH_TOT;

__device__ float g_scratch[SCRATCH_FLOATS];

__device__ __forceinline__ float sigmoidf_(float x) {
    return 1.f / (1.f + __expf(-x));
}
__device__ __forceinline__ ull fma2_(ull a, ull b, ull c) {
    ull d;
    asm("fma.rn.f32x2 %0, %1, %2, %3;" : "=l"(d) : "l"(a), "l"(b), "l"(c));
    return d;
}
__device__ __forceinline__ float hadd2_(ull a) {
    unsigned lo, hi;
    asm("mov.b64 {%0, %1}, %2;" : "=r"(lo), "=r"(hi) : "l"(a));
    return __uint_as_float(lo) + __uint_as_float(hi);
}
__device__ __forceinline__ void mma_bf16(float c[4],
    uint a0, uint a1, uint a2, uint a3, uint b0, uint b1)
{
    asm volatile(
        "mma.sync.aligned.m16n8k16.row.col.f32.bf16.bf16.f32 "
        "{%0,%1,%2,%3},{%4,%5,%6,%7},{%8,%9},{%0,%1,%2,%3};"
        : "+f"(c[0]), "+f"(c[1]), "+f"(c[2]), "+f"(c[3])
        : "r"(a0), "r"(a1), "r"(a2), "r"(a3), "r"(b0), "r"(b1));
}
__device__ __forceinline__ void ldsm_x4(uint& r0, uint& r1, uint& r2, uint& r3,
                                        const void* p)
{
    uint a = (uint)__cvta_generic_to_shared(p);
    asm volatile("ldmatrix.sync.aligned.m8n8.x4.shared.b16 {%0,%1,%2,%3},[%4];"
                 : "=r"(r0), "=r"(r1), "=r"(r2), "=r"(r3) : "r"(a));
}
__device__ __forceinline__ void ldsm_x2t(uint& r0, uint& r1, const void* p)
{
    uint a = (uint)__cvta_generic_to_shared(p);
    asm volatile("ldmatrix.sync.aligned.m8n8.x2.trans.shared.b16 {%0,%1},[%2];"
                 : "=r"(r0), "=r"(r1) : "r"(a));
}
__device__ __forceinline__ void split4(float4 v, uint& h01, uint& h23,
                                       uint& l01, uint& l23)
{
    __nv_bfloat162 h01b = __floats2bfloat162_rn(v.x, v.y);
    __nv_bfloat162 h23b = __floats2bfloat162_rn(v.z, v.w);
    float r0 = v.x - __bfloat162float(h01b.x);
    float r1 = v.y - __bfloat162float(h01b.y);
    float r2 = v.z - __bfloat162float(h23b.x);
    float r3 = v.w - __bfloat162float(h23b.y);
    __nv_bfloat162 l01b = __floats2bfloat162_rn(r0, r1);
    __nv_bfloat162 l23b = __floats2bfloat162_rn(r2, r3);
    h01 = *(uint*)&h01b;  h23 = *(uint*)&h23b;
    l01 = *(uint*)&l01b;  l23 = *(uint*)&l23b;
}

#define A_STRIDE 12
#define B_STRIDE 68

__global__ __launch_bounds__(256) void gemm_tc(
    const float* __restrict__ Aext, size_t Aoff,
    const float* __restrict__ W0, const float* __restrict__ W1,
    const float* __restrict__ W2,
    float* __restrict__ Cext, size_t Coff, int nblk,
    int M, int N, int K, int act)
{
    const float* A = Aext ? Aext : (const float*)g_scratch + Aoff;
    const int which = blockIdx.x / nblk;
    const float* W = (which == 0) ? W0 : (which == 1) ? W1 : W2;
    float* C = Cext ? Cext : g_scratch + Coff + (size_t)which * NM;

    __shared__ __align__(16) uint As[2][2][128][A_STRIDE];
    __shared__ __align__(16) uint Bs[2][2][16][B_STRIDE];

    const int tid  = threadIdx.x;
    const int brow = blockIdx.y * 128;
    const int bcol = (blockIdx.x % nblk) * 128;
    const int lane = tid & 31;
    const int warp = tid >> 5;
    const int wm   = warp >> 2;
    const int wn   = warp & 3;
    const int gid  = lane >> 2;
    const int tig  = lane & 3;
    const int am0 = tid >> 2;
    const int ak0 = (tid & 3) << 2;
    const int bk0 = tid >> 5;
    const int bn0 = (tid & 31) << 2;

    const float* ApA = A + (size_t)(brow + am0) * K + ak0;
    const float* ApB = ApA + (size_t)64 * K;
    const float* BpA = W + (size_t)bk0 * N + bcol + bn0;
    const float* BpB = BpA + (size_t)8 * N;

    float acc[4][4][4];
#pragma unroll
    for (int i = 0; i < 4; i++)
#pragma unroll
        for (int j = 0; j < 4; j++)
#pragma unroll
            for (int c = 0; c < 4; c++) acc[i][j][c] = 0.f;

    const int a_lrow = lane & 15;
    const int a_koff = (lane >> 4) * 4;
    const int b_lrow = lane & 15;

    float4 avA, avB, bvA, bvB;
    avA = *(const float4*)(ApA);
    avB = *(const float4*)(ApB);
    bvA = *(const float4*)(BpA);
    bvB = *(const float4*)(BpB);
    {
        uint h01, h23, l01, l23;
        split4(avA, h01, h23, l01, l23);
        *(uint2*)&As[0][0][am0][ak0 >> 1]      = make_uint2(h01, h23);
        *(uint2*)&As[0][1][am0][ak0 >> 1]      = make_uint2(l01, l23);
        split4(avB, h01, h23, l01, l23);
        *(uint2*)&As[0][0][am0 + 64][ak0 >> 1] = make_uint2(h01, h23);
        *(uint2*)&As[0][1][am0 + 64][ak0 >> 1] = make_uint2(l01, l23);
        split4(bvA, h01, h23, l01, l23);
        *(uint2*)&Bs[0][0][bk0][bn0 >> 1]      = make_uint2(h01, h23);
        *(uint2*)&Bs[0][1][bk0][bn0 >> 1]      = make_uint2(l01, l23);
        split4(bvB, h01, h23, l01, l23);
        *(uint2*)&Bs[0][0][bk0 + 8][bn0 >> 1]  = make_uint2(h01, h23);
        *(uint2*)&Bs[0][1][bk0 + 8][bn0 >> 1]  = make_uint2(l01, l23);
    }
    __syncthreads();

    const int nk = K >> 4;
    for (int kt = 0; kt < nk; kt++) {
        const int buf = kt & 1;
        if (kt + 1 < nk) {
            const int ko = (kt + 1) << 4;
            avA = *(const float4*)(ApA + ko);
            avB = *(const float4*)(ApB + ko);
            bvA = *(const float4*)(BpA + (size_t)ko * N);
            bvB = *(const float4*)(BpB + (size_t)ko * N);
        }
        uint Ah[4][4], Al[4][4], Bh[4][2], Bl[4][2];
#pragma unroll
        for (int mt = 0; mt < 4; mt++) {
            int row = wm * 64 + mt * 16 + a_lrow;
            ldsm_x4(Ah[mt][0], Ah[mt][1], Ah[mt][2], Ah[mt][3],
                    &As[buf][0][row][a_koff]);
            ldsm_x4(Al[mt][0], Al[mt][1], Al[mt][2], Al[mt][3],
                    &As[buf][1][row][a_koff]);
        }
#pragma unroll
        for (int nt = 0; nt < 4; nt++) {
            int nu = wn * 16 + nt * 4;
            ldsm_x2t(Bh[nt][0], Bh[nt][1], &Bs[buf][0][b_lrow][nu]);
            ldsm_x2t(Bl[nt][0], Bl[nt][1], &Bs[buf][1][b_lrow][nu]);
        }
#pragma unroll
        for (int mt = 0; mt < 4; mt++) {
#pragma unroll
            for (int nt = 0; nt < 4; nt++) {
                mma_bf16(acc[mt][nt], Ah[mt][0], Ah[mt][1], Ah[mt][2], Ah[mt][3],
                         Bh[nt][0], Bh[nt][1]);
                mma_bf16(acc[mt][nt], Ah[mt][0], Ah[mt][1], Ah[mt][2], Ah[mt][3],
                         Bl[nt][0], Bl[nt][1]);
                mma_bf16(acc[mt][nt], Al[mt][0], Al[mt][1], Al[mt][2], Al[mt][3],
                         Bh[nt][0], Bh[nt][1]);
            }
        }
        if (kt + 1 < nk) {
            const int nb = buf ^ 1;
            uint h01, h23, l01, l23;
            split4(avA, h01, h23, l01, l23);
            *(uint2*)&As[nb][0][am0][ak0 >> 1]      = make_uint2(h01, h23);
            *(uint2*)&As[nb][1][am0][ak0 >> 1]      = make_uint2(l01, l23);
            split4(avB, h01, h23, l01, l23);
            *(uint2*)&As[nb][0][am0 + 64][ak0 >> 1] = make_uint2(h01, h23);
            *(uint2*)&As[nb][1][am0 + 64][ak0 >> 1] = make_uint2(l01, l23);
            split4(bvA, h01, h23, l01, l23);
            *(uint2*)&Bs[nb][0][bk0][bn0 >> 1]      = make_uint2(h01, h23);
            *(uint2*)&Bs[nb][1][bk0][bn0 >> 1]      = make_uint2(l01, l23);
            split4(bvB, h01, h23, l01, l23);
            *(uint2*)&Bs[nb][0][bk0 + 8][bn0 >> 1]  = make_uint2(h01, h23);
            *(uint2*)&Bs[nb][1][bk0 + 8][bn0 >> 1]  = make_uint2(l01, l23);
            __syncthreads();
        }
    }
#pragma unroll
    for (int mt = 0; mt < 4; mt++) {
        int row0 = brow + wm * 64 + mt * 16 + gid;
#pragma unroll
        for (int nt = 0; nt < 4; nt++) {
            int col0 = bcol + wn * 32 + nt * 8 + 2 * tig;
            float c0 = acc[mt][nt][0], c1 = acc[mt][nt][1];
            float c2 = acc[mt][nt][2], c3 = acc[mt][nt][3];
            if (act == 1) {
                c0 *= sigmoidf_(c0); c1 *= sigmoidf_(c1);
                c2 *= sigmoidf_(c2); c3 *= sigmoidf_(c3);
            } else if (act == 2) {
                c0 = sigmoidf_(c0); c1 = sigmoidf_(c1);
                c2 = sigmoidf_(c2); c3 = sigmoidf_(c3);
            }
            *(float2*)(C + (size_t)row0 * N + col0)       = make_float2(c0, c1);
            *(float2*)(C + (size_t)(row0 + 8) * N + col0) = make_float2(c2, c3);
        }
    }
}

__global__ __launch_bounds__(256) void ab_kernel(
    const float* __restrict__ x,
    const float* __restrict__ Wa, const float* __restrict__ ba,
    const float* __restrict__ Wb, const float* __restrict__ bb)
{
    int row  = blockIdx.x * 8 + (threadIdx.x >> 5);
    int lane = threadIdx.x & 31;
    const float* xr = x + (size_t)row * DDIM;
    const float* W  = (lane < 16) ? Wa : Wb;
    int h = lane & 15;
    float s0 = 0.f, s1 = 0.f, s2 = 0.f, s3 = 0.f;
#pragma unroll 4
    for (int i = 0; i < DDIM; i += 4) {
        s0 = fmaf(xr[i + 0], W[(i + 0) * HDIM + h], s0);
        s1 = fmaf(xr[i + 1], W[(i + 1) * HDIM + h], s1);
        s2 = fmaf(xr[i + 2], W[(i + 2) * HDIM + h], s2);
        s3 = fmaf(xr[i + 3], W[(i + 3) * HDIM + h], s3);
    }
    float s = (s0 + s1) + (s2 + s3);
    if (lane < 16) {
        float sg = sigmoidf_(s + ba[h]);
        g_scratch[OF_A + (size_t)row * HDIM + h] = fminf(fmaxf(sg, 0.1f), 1.0f);
    } else {
        float sg = sigmoidf_(s + bb[h]);
        g_scratch[OF_B + (size_t)row * HDIM + h] = fminf(sg, 1.0f);
    }
}

__global__ __launch_bounds__(512) void conv_kernel(
    const float* __restrict__ qcw, const float* __restrict__ qcb,
    const float* __restrict__ kcw, const float* __restrict__ kcb,
    const float* __restrict__ vcw, const float* __restrict__ vcb)
{
    int which = blockIdx.y;
    const float* w;
    const float* bias;
    size_t pre_off, out_off;
    int do_norm;
    if (which == 0) { w = qcw; bias = qcb; pre_off = OF_Q; out_off = OF_QN; do_norm = 1; }
    else if (which == 1) { w = kcw; bias = kcb; pre_off = OF_K; out_off = OF_KN; do_norm = 1; }
    else { w = vcw; bias = vcb; pre_off = OF_V; out_off = OF_VN; do_norm = 0; }

    const float* pre = (const float*)g_scratch + pre_off;
    float*       out = g_scratch + out_off;
    int row  = blockIdx.x;
    int t    = row & (TDIM - 1);
    int lane = threadIdx.x & 31;
    int h    = threadIdx.x >> 5;
    int c0   = h * 64 + lane;
    int c1   = c0 + 32;

    const float* p = pre + (size_t)row * DDIM;
    float v0 = bias[c0], v1 = bias[c1];
#pragma unroll
    for (int kk = 0; kk < 4; kk++) {
        int dt = kk - 3;
        if (t + dt >= 0) {
            const float* pr = p + (ptrdiff_t)dt * DDIM;
            v0 = fmaf(w[c0 * 4 + kk], pr[c0], v0);
            v1 = fmaf(w[c1 * 4 + kk], pr[c1], v1);
        }
    }
    v0 *= sigmoidf_(v0);
    v1 *= sigmoidf_(v1);
    if (do_norm) {
        float ss = v0 * v0 + v1 * v1;
#pragma unroll
        for (int o = 16; o > 0; o >>= 1) ss += __shfl_xor_sync(0xffffffffu, ss, o);
        float inv = 1.f / fmaxf(sqrtf(ss), 1e-6f);
        v0 *= inv; v1 *= inv;
    }
    out[(size_t)row * DDIM + c0] = v0;
    out[(size_t)row * DDIM + c1] = v1;
}

// ---------------------------------------------------------------------------
// prep_kernel: one CTA per chunk. P/AQ/GkT dots; then (I+M)[Uv|W]=[bV|bApK]
// via REGISTER-RESIDENT forward substitution (1 column/thread, full unroll).
// smem ~53KB (4 CTAs/SM).
// ---------------------------------------------------------------------------
__global__ __launch_bounds__(256) void prep_kernel()
{
    extern __shared__ float sm[];
    float* Kc  = sm;                 // [64][68]
    float* Qv  = sm + 4352;          // [64][68]  Q, then V, then Uv stage
    float* MM  = sm + 8704;          // [64][68]  M, then W stage
    float* sLc = sm + 13056;         // inclusive cumsum log2(a)
    float* sLp = sm + 13120;         // exclusive
    float* sbv = sm + 13184;         // beta
    float* sbp = sm + 13248;         // beta * exp2(Lp)

    const float* Qn = g_scratch + OF_QN;
    const float* Kn = g_scratch + OF_KN;
    const float* Vn = g_scratch + OF_VN;
    const float* Al = g_scratch + OF_A;
    const float* Be = g_scratch + OF_B;

    int cid = blockIdx.x;
    int bh = cid >> 6, ci = cid & 63;
    int b = bh >> 4, h = bh & 15;
    int t0 = ci << 6;
    size_t base  = (size_t)b * TDIM * DDIM + (size_t)h * 64 + (size_t)t0 * DDIM;
    size_t abase = (size_t)b * TDIM * HDIM + h + (size_t)t0 * HDIM;
    int tid = threadIdx.x;

    if (tid < 64) {
        sLc[tid] = log2f(Al[abase + (size_t)tid * HDIM]);
        sbv[tid] = Be[abase + (size_t)tid * HDIM];
    }
    __syncthreads();
    if (tid == 0) {
        float run = 0.f;
        for (int i = 0; i < 64; i++) { sLp[i] = run; run += sLc[i]; sLc[i] = run; }
    }
    // load K, Q
    {
        int row = tid >> 4;
        int col = (tid & 15) << 2;
        for (int rr = 0; rr < 4; rr++) {
            int r = row + rr * 16;
            *(float4*)&Kc[r * 68 + col] = *(const float4*)(Kn + base + (size_t)r * DDIM + col);
            *(float4*)&Qv[r * 68 + col] = *(const float4*)(Qn + base + (size_t)r * DDIM + col);
        }
    }
    __syncthreads();
    if (tid < 64) sbp[tid] = sbv[tid] * exp2f(sLp[tid]);

    float* Pg  = g_scratch + OF_PG  + (size_t)cid * 4096;
    float* AQg = g_scratch + OF_AQG + (size_t)cid * 4096;
    float* Gg  = g_scratch + OF_GKT + (size_t)cid * 4096;
    float* Wg  = g_scratch + OF_WTG + (size_t)cid * 4096;
    float* Ug  = g_scratch + OF_UVT + (size_t)cid * 4096;

    float Lc63 = sLc[63];
    // P[t][i] (i<=t), AQ[t][k], GkT[r][i]
    for (int kq = 0; kq < 16; kq++) {
        int e = kq * 256 + tid;
        int t = e >> 6, i = e & 63;
        float pv = 0.f;
        if (i <= t) {
            ull a0 = 0, a1 = 0;
#pragma unroll 8
            for (int m = 0; m < 64; m += 4) {
                a0 = fma2_(*(ull*)&Qv[t * 68 + m],     *(ull*)&Kc[i * 68 + m],     a0);
                a1 = fma2_(*(ull*)&Qv[t * 68 + m + 2], *(ull*)&Kc[i * 68 + m + 2], a1);
            }
            pv = exp2f(sLc[t] - sLc[i]) * (hadd2_(a0) + hadd2_(a1));
        }
        Pg[e]  = pv;
        AQg[e] = exp2f(sLc[t]) * Qv[t * 68 + i];
        Gg[e]  = exp2f(Lc63 - sLc[i]) * Kc[i * 68 + t];
    }
    __syncthreads();
    // load V over Qv
    {
        int row = tid >> 4;
        int col = (tid & 15) << 2;
        for (int rr = 0; rr < 4; rr++) {
            int r = row + rr * 16;
            *(float4*)&Qv[r * 68 + col] = *(const float4*)(Vn + base + (size_t)r * DDIM + col);
        }
    }
    __syncthreads();
    // MM (strictly lower)
    for (int kq = 0; kq < 16; kq++) {
        int e = kq * 256 + tid;
        int i = e >> 6, j = e & 63;
        if (j < i) {
            ull a0 = 0, a1 = 0;
#pragma unroll 8
            for (int m = 0; m < 64; m += 4) {
                a0 = fma2_(*(ull*)&Kc[i * 68 + m],     *(ull*)&Kc[j * 68 + m],     a0);
                a1 = fma2_(*(ull*)&Kc[i * 68 + m + 2], *(ull*)&Kc[j * 68 + m + 2], a1);
            }
            MM[i * 68 + j] = sbv[i] * exp2f(sLp[i] - sLc[j]) * (hadd2_(a0) + hadd2_(a1));
        }
    }
    __syncthreads();

    // register-resident forward substitution: thread c owns RHS column c.
    // c<64: Uv column (b*V); c>=64: W column (b*Aprev*K).
    float xr[64];
    if (tid < 128) {
        int c = tid;
        if (c < 64) {
#pragma unroll
            for (int i = 0; i < 64; i++) xr[i] = sbv[i] * Qv[i * 68 + c];
        } else {
            int k = c - 64;
#pragma unroll
            for (int i = 0; i < 64; i++) xr[i] = sbp[i] * Kc[i * 68 + k];
        }
#pragma unroll
        for (int i = 1; i < 64; i++) {
            float a0 = 0.f, a1 = 0.f;
#pragma unroll
            for (int j = 0; j + 1 < i; j += 2) {
                a0 = fmaf(MM[i * 68 + j],     xr[j],     a0);
                a1 = fmaf(MM[i * 68 + j + 1], xr[j + 1], a1);
            }
            if (i & 1) a0 = fmaf(MM[i * 68 + (i - 1)], xr[i - 1], a0);
            xr[i] -= (a0 + a1);
        }
    }
    __syncthreads();   // everyone done reading MM/Qv/Kc
    // stage: Uv col c -> Qv[c][i] (row-major per column); W col k -> MM[i][k]
    if (tid < 64) {
        int c = tid;
#pragma unroll
        for (int i = 0; i < 64; i++) Qv[c * 68 + i] = xr[i];
    } else if (tid < 128) {
        int k = tid - 64;
#pragma unroll
        for (int i = 0; i < 64; i++) MM[i * 68 + k] = xr[i];
    }
    __syncthreads();
    // coalesced writes: Ug[c*64+i] = Qv[c][i]; Wg[i*64+k] = MM[i][k]
    for (int kq = 0; kq < 16; kq++) {
        int e = kq * 256 + tid;
        { int c = e >> 6, i = e & 63; Ug[e] = Qv[c * 68 + i]; }
        { int i = e >> 6, kk = e & 63; Wg[e] = MM[i * 68 + kk]; }
    }
    if (tid == 0) g_scratch[OF_ACG + cid] = exp2f(Lc63);
}

// ---------------------------------------------------------------------------
// scan_kernel: 128 CTAs, 128 threads, sequential over 64 chunks.
// ---------------------------------------------------------------------------
__global__ __launch_bounds__(128) void scan_kernel()
{
    extern __shared__ float sm[];
    float* mW  = sm;
    float* mAQ = sm + 4352;
    float* mP  = sm + 8704;
    float* mG  = sm + 13056;
    float* S_T = sm + 17408;
    float* U_T = sm + 18496;

    int blk = blockIdx.x;
    int bh = blk >> 2, cq = blk & 3;
    int c0 = cq << 4;
    int b = bh >> 4, h = bh & 15;
    size_t obase = (size_t)b * TDIM * DDIM + (size_t)h * 64;
    int tid = threadIdx.x;
    int cc = tid & 15, grp = tid >> 4;

    for (int e = tid; e < 16 * 68; e += 128) S_T[e] = 0.f;
    __syncthreads();

    float* O = g_scratch + OF_O;

    for (int ch = 0; ch < NCHUNK; ch++) {
        int cid = bh * 64 + ch;
        const float* Wg  = g_scratch + OF_WTG + (size_t)cid * 4096;
        const float* AQg = g_scratch + OF_AQG + (size_t)cid * 4096;
        const float* Pg  = g_scratch + OF_PG  + (size_t)cid * 4096;
        const float* Gg  = g_scratch + OF_GKT + (size_t)cid * 4096;
        const float* Ug  = g_scratch + OF_UVT + (size_t)cid * 4096;

        for (int kq = 0; kq < 8; kq++) {
            int e4 = kq * 128 + tid;
            int r = e4 >> 4, c4 = (e4 & 15) << 2;
            *(float4*)&mW[r * 68 + c4]  = *(const float4*)(Wg  + r * 64 + c4);
            *(float4*)&mAQ[r * 68 + c4] = *(const float4*)(AQg + r * 64 + c4);
            *(float4*)&mP[r * 68 + c4]  = *(const float4*)(Pg  + r * 64 + c4);
            *(float4*)&mG[r * 68 + c4]  = *(const float4*)(Gg  + r * 64 + c4);
        }
        for (int kq = 0; kq < 2; kq++) {
            int e4 = kq * 128 + tid;
            int r = e4 >> 4, c4 = (e4 & 15) << 2;
            *(float4*)&U_T[r * 68 + c4] = *(const float4*)(Ug + (size_t)(c0 + r) * 64 + c4);
        }
        float AC = g_scratch[OF_ACG + cid];
        __syncthreads();

        {
            ull aU[8][2];
#pragma unroll
            for (int ii = 0; ii < 8; ii++) { aU[ii][0] = 0; aU[ii][1] = 0; }
#pragma unroll
            for (int k4 = 0; k4 < 16; k4++) {
                ull s01 = *(ull*)&S_T[cc * 68 + k4 * 4];
                ull s23 = *(ull*)&S_T[cc * 68 + k4 * 4 + 2];
#pragma unroll
                for (int ii = 0; ii < 8; ii++) {
                    int i = grp * 8 + ii;
                    aU[ii][0] = fma2_(*(ull*)&mW[i * 68 + k4 * 4],     s01, aU[ii][0]);
                    aU[ii][1] = fma2_(*(ull*)&mW[i * 68 + k4 * 4 + 2], s23, aU[ii][1]);
                }
            }
#pragma unroll
            for (int ii = 0; ii < 8; ii++) {
                int i = grp * 8 + ii;
                U_T[cc * 68 + i] -= (hadd2_(aU[ii][0]) + hadd2_(aU[ii][1]));
            }
        }
        float oacc[8];
        {
            ull aO[8][2];
#pragma unroll
            for (int ii = 0; ii < 8; ii++) { aO[ii][0] = 0; aO[ii][1] = 0; }
#pragma unroll
            for (int k4 = 0; k4 < 16; k4++) {
                ull s01 = *(ull*)&S_T[cc * 68 + k4 * 4];
                ull s23 = *(ull*)&S_T[cc * 68 + k4 * 4 + 2];
#pragma unroll
                for (int ii = 0; ii < 8; ii++) {
                    int t = grp * 8 + ii;
                    aO[ii][0] = fma2_(*(ull*)&mAQ[t * 68 + k4 * 4],     s01, aO[ii][0]);
                    aO[ii][1] = fma2_(*(ull*)&mAQ[t * 68 + k4 * 4 + 2], s23, aO[ii][1]);
                }
            }
#pragma unroll
            for (int ii = 0; ii < 8; ii++)
                oacc[ii] = hadd2_(aO[ii][0]) + hadd2_(aO[ii][1]);
        }
        __syncthreads();
        {
            ull aO[8][2];
#pragma unroll
            for (int ii = 0; ii < 8; ii++) { aO[ii][0] = 0; aO[ii][1] = 0; }
#pragma unroll
            for (int k4 = 0; k4 < 16; k4++) {
                ull u01 = *(ull*)&U_T[cc * 68 + k4 * 4];
                ull u23 = *(ull*)&U_T[cc * 68 + k4 * 4 + 2];
#pragma unroll
                for (int ii = 0; ii < 8; ii++) {
                    int t = grp * 8 + ii;
                    aO[ii][0] = fma2_(*(ull*)&mP[t * 68 + k4 * 4],     u01, aO[ii][0]);
                    aO[ii][1] = fma2_(*(ull*)&mP[t * 68 + k4 * 4 + 2], u23, aO[ii][1]);
                }
            }
#pragma unroll
            for (int ii = 0; ii < 8; ii++) {
                int t = grp * 8 + ii;
                float ov = oacc[ii] + hadd2_(aO[ii][0]) + hadd2_(aO[ii][1]);
                O[obase + (size_t)(ch * 64 + t) * DDIM + c0 + cc] = ov;
            }
        }
        {
            ull aS[8][2];
#pragma unroll
            for (int ii = 0; ii < 8; ii++) { aS[ii][0] = 0; aS[ii][1] = 0; }
#pragma unroll
            for (int k4 = 0; k4 < 16; k4++) {
                ull u01 = *(ull*)&U_T[cc * 68 + k4 * 4];
                ull u23 = *(ull*)&U_T[cc * 68 + k4 * 4 + 2];
#pragma unroll
                for (int ii = 0; ii < 8; ii++) {
                    int r = grp * 8 + ii;
                    aS[ii][0] = fma2_(*(ull*)&mG[r * 68 + k4 * 4],     u01, aS[ii][0]);
                    aS[ii][1] = fma2_(*(ull*)&mG[r * 68 + k4 * 4 + 2], u23, aS[ii][1]);
                }
            }
#pragma unroll
            for (int ii = 0; ii < 8; ii++) {
                int r = grp * 8 + ii;
                S_T[cc * 68 + r] = AC * S_T[cc * 68 + r]
                                   + hadd2_(aS[ii][0]) + hadd2_(aS[ii][1]);
            }
        }
        __syncthreads();
    }
}

__global__ __launch_bounds__(512) void post_kernel(const float* __restrict__ rms_w)
{
    const float* O  = g_scratch + OF_O;
    const float* G  = g_scratch + OF_G;
    float*       Og = g_scratch + OF_OG;
    int row  = blockIdx.x;
    int lane = threadIdx.x & 31;
    int h    = threadIdx.x >> 5;
    size_t i0 = (size_t)row * DDIM + h * 64 + lane;
    float v0 = O[i0], v1 = O[i0 + 32];
    float ss = v0 * v0 + v1 * v1;
#pragma unroll
    for (int o = 16; o > 0; o >>= 1) ss += __shfl_xor_sync(0xffffffffu, ss, o);
    float inv = rsqrtf(ss * (1.f / 64.f) + 1e-6f);
    v0 = v0 * inv * rms_w[h * 64 + lane]      * G[i0];
    v1 = v1 * inv * rms_w[h * 64 + lane + 32] * G[i0 + 32];
    Og[i0]      = v0;
    Og[i0 + 32] = v1;
}

extern "C" void kernel_launch(void* const* d_in, const int* in_sizes, int n_in,
                              void* d_out, int out_size)
{
    (void)in_sizes; (void)n_in; (void)out_size;
    const float* x   = (const float*)d_in[0];
    const float* Wq  = (const float*)d_in[1];
    const float* Wk  = (const float*)d_in[2];
    const float* Wv  = (const float*)d_in[3];
    const float* Wo  = (const float*)d_in[4];
    const float* Wa  = (const float*)d_in[5];
    const float* ba  = (const float*)d_in[6];
    const float* Wb  = (const float*)d_in[7];
    const float* bb  = (const float*)d_in[8];
    const float* Wgd = (const float*)d_in[9];
    const float* Wgu = (const float*)d_in[10];
    const float* rms = (const float*)d_in[11];
    const float* qcw = (const float*)d_in[12];
    const float* qcb = (const float*)d_in[13];
    const float* kcw = (const float*)d_in[14];
    const float* kcb = (const float*)d_in[15];
    const float* vcw = (const float*)d_in[16];
    const float* vcb = (const float*)d_in[17];
    float* out = (float*)d_out;

    cudaFuncSetAttribute(prep_kernel, cudaFuncAttributeMaxDynamicSharedMemorySize, 57344);
    cudaFuncSetAttribute(scan_kernel, cudaFuncAttributeMaxDynamicSharedMemorySize, 81920);

    // 1) alpha/beta
    ab_kernel<<<MROWS / 8, 256>>>(x, Wa, ba, Wb, bb);
    // 2) fused QKV projection
    {
        dim3 gqkv(24, MROWS / 128);
        gemm_tc<<<gqkv, 256>>>(x, 0, Wq, Wk, Wv, nullptr, OF_Q, 8,
                               MROWS, 1024, 1024, 0);
    }
    // 3) conv
    {
        dim3 gc(MROWS, 3);
        conv_kernel<<<gc, 512>>>(qcw, qcb, kcw, kcb, vcw, vcb);
    }
    // 4) chunk prep (parallel)  <-- ncu capture slot
    prep_kernel<<<NCH_TOT, 256, 57344>>>();
    // 5) chunk scan
    scan_kernel<<<BDIM * HDIM * 4, 128, 81920>>>();
    // 6-7) gate MLP
    {
        dim3 g512g(4, MROWS / 128);
        gemm_tc<<<g512g, 256>>>(x, 0, Wgd, Wgd, Wgd, nullptr, OF_XG, 4,
                                MROWS, 512, 1024, 1);
    }
    {
        dim3 g1024g(8, MROWS / 128);
        gemm_tc<<<g1024g, 256>>>(nullptr, OF_XG, Wgu, Wgu, Wgu, nullptr, OF_G, 8,
                                 MROWS, 1024, 512, 2);
    }
    // 8) RMSNorm + gate
    post_kernel<<<MROWS, 512>>>(rms);
    // 9) output projection
    {
        dim3 g1024g(8, MROWS / 128);
        gemm_tc<<<g1024g, 256>>>(nullptr, OF_OG, Wo, Wo, Wo, out, 0, 8,
                                 MROWS, 1024, 1024, 0);
    }
}

// round 14
// speedup vs baseline: 1.6024x; 1.0060x over previous
#include <cuda_runtime.h>
#include <cuda_bf16.h>

// ---------------------------------------------------------------------------
// GatedDeltaNet (B=2,T=4096,D=1024,H=16,DK=DV=64,KS=4)
// Round 14: prep dot phases -> 4x4 register tiles (4x less LDS traffic) and
// table-based exp2 (no in-loop MUFU). Everything else = round-13 winner.
// ---------------------------------------------------------------------------

#define TDIM 4096
#define BDIM 2
#define HDIM 16
#define DDIM 1024
#define MROWS (BDIM * TDIM)
#define NCHUNK 64
#define NCH_TOT (BDIM * HDIM * NCHUNK)   // 2048

typedef unsigned long long ull;
typedef unsigned int uint;

static constexpr size_t NM   = (size_t)MROWS * DDIM;
static constexpr size_t OF_Q  = 0;
static constexpr size_t OF_K  = 1 * NM;
static constexpr size_t OF_V  = 2 * NM;
static constexpr size_t OF_QN = 3 * NM;
static constexpr size_t OF_KN = 4 * NM;
static constexpr size_t OF_VN = 5 * NM;
static constexpr size_t OF_G  = 6 * NM;
static constexpr size_t OF_O  = 7 * NM;
static constexpr size_t OF_OG = 8 * NM;
static constexpr size_t OF_XG = 9 * NM;
static constexpr size_t OF_A  = OF_XG + (size_t)MROWS * 512;
static constexpr size_t OF_B  = OF_A + (size_t)MROWS * HDIM;
static constexpr size_t CHMAT = (size_t)NCH_TOT * 4096;
static constexpr size_t OF_PG  = OF_B + (size_t)MROWS * HDIM;
static constexpr size_t OF_AQG = OF_PG + CHMAT;
static constexpr size_t OF_GKT = OF_AQG + CHMAT;
static constexpr size_t OF_WTG = OF_GKT + CHMAT;
static constexpr size_t OF_UVT = OF_WTG + CHMAT;
static constexpr size_t OF_ACG = OF_UVT + CHMAT;
static constexpr size_t SCRATCH_FLOATS = OF_ACG + NCH_TOT;

__device__ float g_scratch[SCRATCH_FLOATS];

__device__ __forceinline__ float sigmoidf_(float x) {
    return 1.f / (1.f + __expf(-x));
}
__device__ __forceinline__ ull fma2_(ull a, ull b, ull c) {
    ull d;
    asm("fma.rn.f32x2 %0, %1, %2, %3;" : "=l"(d) : "l"(a), "l"(b), "l"(c));
    return d;
}
__device__ __forceinline__ float hadd2_(ull a) {
    unsigned lo, hi;
    asm("mov.b64 {%0, %1}, %2;" : "=r"(lo), "=r"(hi) : "l"(a));
    return __uint_as_float(lo) + __uint_as_float(hi);
}
__device__ __forceinline__ void mma_bf16(float c[4],
    uint a0, uint a1, uint a2, uint a3, uint b0, uint b1)
{
    asm volatile(
        "mma.sync.aligned.m16n8k16.row.col.f32.bf16.bf16.f32 "
        "{%0,%1,%2,%3},{%4,%5,%6,%7},{%8,%9},{%0,%1,%2,%3};"
        : "+f"(c[0]), "+f"(c[1]), "+f"(c[2]), "+f"(c[3])
        : "r"(a0), "r"(a1), "r"(a2), "r"(a3), "r"(b0), "r"(b1));
}
__device__ __forceinline__ void ldsm_x4(uint& r0, uint& r1, uint& r2, uint& r3,
                                        const void* p)
{
    uint a = (uint)__cvta_generic_to_shared(p);
    asm volatile("ldmatrix.sync.aligned.m8n8.x4.shared.b16 {%0,%1,%2,%3},[%4];"
                 : "=r"(r0), "=r"(r1), "=r"(r2), "=r"(r3) : "r"(a));
}
__device__ __forceinline__ void ldsm_x2t(uint& r0, uint& r1, const void* p)
{
    uint a = (uint)__cvta_generic_to_shared(p);
    asm volatile("ldmatrix.sync.aligned.m8n8.x2.trans.shared.b16 {%0,%1},[%2];"
                 : "=r"(r0), "=r"(r1) : "r"(a));
}
__device__ __forceinline__ void split4(float4 v, uint& h01, uint& h23,
                                       uint& l01, uint& l23)
{
    __nv_bfloat162 h01b = __floats2bfloat162_rn(v.x, v.y);
    __nv_bfloat162 h23b = __floats2bfloat162_rn(v.z, v.w);
    float r0 = v.x - __bfloat162float(h01b.x);
    float r1 = v.y - __bfloat162float(h01b.y);
    float r2 = v.z - __bfloat162float(h23b.x);
    float r3 = v.w - __bfloat162float(h23b.y);
    __nv_bfloat162 l01b = __floats2bfloat162_rn(r0, r1);
    __nv_bfloat162 l23b = __floats2bfloat162_rn(r2, r3);
    h01 = *(uint*)&h01b;  h23 = *(uint*)&h23b;
    l01 = *(uint*)&l01b;  l23 = *(uint*)&l23b;
}

#define A_STRIDE 12
#define B_STRIDE 68

__global__ __launch_bounds__(256) void gemm_tc(
    const float* __restrict__ Aext, size_t Aoff,
    const float* __restrict__ W0, const float* __restrict__ W1,
    const float* __restrict__ W2,
    float* __restrict__ Cext, size_t Coff, int nblk,
    int M, int N, int K, int act)
{
    const float* A = Aext ? Aext : (const float*)g_scratch + Aoff;
    const int which = blockIdx.x / nblk;
    const float* W = (which == 0) ? W0 : (which == 1) ? W1 : W2;
    float* C = Cext ? Cext : g_scratch + Coff + (size_t)which * NM;

    __shared__ __align__(16) uint As[2][2][128][A_STRIDE];
    __shared__ __align__(16) uint Bs[2][2][16][B_STRIDE];

    const int tid  = threadIdx.x;
    const int brow = blockIdx.y * 128;
    const int bcol = (blockIdx.x % nblk) * 128;
    const int lane = tid & 31;
    const int warp = tid >> 5;
    const int wm   = warp >> 2;
    const int wn   = warp & 3;
    const int gid  = lane >> 2;
    const int tig  = lane & 3;
    const int am0 = tid >> 2;
    const int ak0 = (tid & 3) << 2;
    const int bk0 = tid >> 5;
    const int bn0 = (tid & 31) << 2;

    const float* ApA = A + (size_t)(brow + am0) * K + ak0;
    const float* ApB = ApA + (size_t)64 * K;
    const float* BpA = W + (size_t)bk0 * N + bcol + bn0;
    const float* BpB = BpA + (size_t)8 * N;

    float acc[4][4][4];
#pragma unroll
    for (int i = 0; i < 4; i++)
#pragma unroll
        for (int j = 0; j < 4; j++)
#pragma unroll
            for (int c = 0; c < 4; c++) acc[i][j][c] = 0.f;

    const int a_lrow = lane & 15;
    const int a_koff = (lane >> 4) * 4;
    const int b_lrow = lane & 15;

    float4 avA, avB, bvA, bvB;
    avA = *(const float4*)(ApA);
    avB = *(const float4*)(ApB);
    bvA = *(const float4*)(BpA);
    bvB = *(const float4*)(BpB);
    {
        uint h01, h23, l01, l23;
        split4(avA, h01, h23, l01, l23);
        *(uint2*)&As[0][0][am0][ak0 >> 1]      = make_uint2(h01, h23);
        *(uint2*)&As[0][1][am0][ak0 >> 1]      = make_uint2(l01, l23);
        split4(avB, h01, h23, l01, l23);
        *(uint2*)&As[0][0][am0 + 64][ak0 >> 1] = make_uint2(h01, h23);
        *(uint2*)&As[0][1][am0 + 64][ak0 >> 1] = make_uint2(l01, l23);
        split4(bvA, h01, h23, l01, l23);
        *(uint2*)&Bs[0][0][bk0][bn0 >> 1]      = make_uint2(h01, h23);
        *(uint2*)&Bs[0][1][bk0][bn0 >> 1]      = make_uint2(l01, l23);
        split4(bvB, h01, h23, l01, l23);
        *(uint2*)&Bs[0][0][bk0 + 8][bn0 >> 1]  = make_uint2(h01, h23);
        *(uint2*)&Bs[0][1][bk0 + 8][bn0 >> 1]  = make_uint2(l01, l23);
    }
    __syncthreads();

    const int nk = K >> 4;
    for (int kt = 0; kt < nk; kt++) {
        const int buf = kt & 1;
        if (kt + 1 < nk) {
            const int ko = (kt + 1) << 4;
            avA = *(const float4*)(ApA + ko);
            avB = *(const float4*)(ApB + ko);
            bvA = *(const float4*)(BpA + (size_t)ko * N);
            bvB = *(const float4*)(BpB + (size_t)ko * N);
        }
        uint Ah[4][4], Al[4][4], Bh[4][2], Bl[4][2];
#pragma unroll
        for (int mt = 0; mt < 4; mt++) {
            int row = wm * 64 + mt * 16 + a_lrow;
            ldsm_x4(Ah[mt][0], Ah[mt][1], Ah[mt][2], Ah[mt][3],
                    &As[buf][0][row][a_koff]);
            ldsm_x4(Al[mt][0], Al[mt][1], Al[mt][2], Al[mt][3],
                    &As[buf][1][row][a_koff]);
        }
#pragma unroll
        for (int nt = 0; nt < 4; nt++) {
            int nu = wn * 16 + nt * 4;
            ldsm_x2t(Bh[nt][0], Bh[nt][1], &Bs[buf][0][b_lrow][nu]);
            ldsm_x2t(Bl[nt][0], Bl[nt][1], &Bs[buf][1][b_lrow][nu]);
        }
#pragma unroll
        for (int mt = 0; mt < 4; mt++) {
#pragma unroll
            for (int nt = 0; nt < 4; nt++) {
                mma_bf16(acc[mt][nt], Ah[mt][0], Ah[mt][1], Ah[mt][2], Ah[mt][3],
                         Bh[nt][0], Bh[nt][1]);
                mma_bf16(acc[mt][nt], Ah[mt][0], Ah[mt][1], Ah[mt][2], Ah[mt][3],
                         Bl[nt][0], Bl[nt][1]);
                mma_bf16(acc[mt][nt], Al[mt][0], Al[mt][1], Al[mt][2], Al[mt][3],
                         Bh[nt][0], Bh[nt][1]);
            }
        }
        if (kt + 1 < nk) {
            const int nb = buf ^ 1;
            uint h01, h23, l01, l23;
            split4(avA, h01, h23, l01, l23);
            *(uint2*)&As[nb][0][am0][ak0 >> 1]      = make_uint2(h01, h23);
            *(uint2*)&As[nb][1][am0][ak0 >> 1]      = make_uint2(l01, l23);
            split4(avB, h01, h23, l01, l23);
            *(uint2*)&As[nb][0][am0 + 64][ak0 >> 1] = make_uint2(h01, h23);
            *(uint2*)&As[nb][1][am0 + 64][ak0 >> 1] = make_uint2(l01, l23);
            split4(bvA, h01, h23, l01, l23);
            *(uint2*)&Bs[nb][0][bk0][bn0 >> 1]      = make_uint2(h01, h23);
            *(uint2*)&Bs[nb][1][bk0][bn0 >> 1]      = make_uint2(l01, l23);
            split4(bvB, h01, h23, l01, l23);
            *(uint2*)&Bs[nb][0][bk0 + 8][bn0 >> 1]  = make_uint2(h01, h23);
            *(uint2*)&Bs[nb][1][bk0 + 8][bn0 >> 1]  = make_uint2(l01, l23);
            __syncthreads();
        }
    }
#pragma unroll
    for (int mt = 0; mt < 4; mt++) {
        int row0 = brow + wm * 64 + mt * 16 + gid;
#pragma unroll
        for (int nt = 0; nt < 4; nt++) {
            int col0 = bcol + wn * 32 + nt * 8 + 2 * tig;
            float c0 = acc[mt][nt][0], c1 = acc[mt][nt][1];
            float c2 = acc[mt][nt][2], c3 = acc[mt][nt][3];
            if (act == 1) {
                c0 *= sigmoidf_(c0); c1 *= sigmoidf_(c1);
                c2 *= sigmoidf_(c2); c3 *= sigmoidf_(c3);
            } else if (act == 2) {
                c0 = sigmoidf_(c0); c1 = sigmoidf_(c1);
                c2 = sigmoidf_(c2); c3 = sigmoidf_(c3);
            }
            *(float2*)(C + (size_t)row0 * N + col0)       = make_float2(c0, c1);
            *(float2*)(C + (size_t)(row0 + 8) * N + col0) = make_float2(c2, c3);
        }
    }
}

__global__ __launch_bounds__(256) void ab_kernel(
    const float* __restrict__ x,
    const float* __restrict__ Wa, const float* __restrict__ ba,
    const float* __restrict__ Wb, const float* __restrict__ bb)
{
    int row  = blockIdx.x * 8 + (threadIdx.x >> 5);
    int lane = threadIdx.x & 31;
    const float* xr = x + (size_t)row * DDIM;
    const float* W  = (lane < 16) ? Wa : Wb;
    int h = lane & 15;
    float s0 = 0.f, s1 = 0.f, s2 = 0.f, s3 = 0.f;
#pragma unroll 4
    for (int i = 0; i < DDIM; i += 4) {
        s0 = fmaf(xr[i + 0], W[(i + 0) * HDIM + h], s0);
        s1 = fmaf(xr[i + 1], W[(i + 1) * HDIM + h], s1);
        s2 = fmaf(xr[i + 2], W[(i + 2) * HDIM + h], s2);
        s3 = fmaf(xr[i + 3], W[(i + 3) * HDIM + h], s3);
    }
    float s = (s0 + s1) + (s2 + s3);
    if (lane < 16) {
        float sg = sigmoidf_(s + ba[h]);
        g_scratch[OF_A + (size_t)row * HDIM + h] = fminf(fmaxf(sg, 0.1f), 1.0f);
    } else {
        float sg = sigmoidf_(s + bb[h]);
        g_scratch[OF_B + (size_t)row * HDIM + h] = fminf(sg, 1.0f);
    }
}

__global__ __launch_bounds__(512) void conv_kernel(
    const float* __restrict__ qcw, const float* __restrict__ qcb,
    const float* __restrict__ kcw, const float* __restrict__ kcb,
    const float* __restrict__ vcw, const float* __restrict__ vcb)
{
    int which = blockIdx.y;
    const float* w;
    const float* bias;
    size_t pre_off, out_off;
    int do_norm;
    if (which == 0) { w = qcw; bias = qcb; pre_off = OF_Q; out_off = OF_QN; do_norm = 1; }
    else if (which == 1) { w = kcw; bias = kcb; pre_off = OF_K; out_off = OF_KN; do_norm = 1; }
    else { w = vcw; bias = vcb; pre_off = OF_V; out_off = OF_VN; do_norm = 0; }

    const float* pre = (const float*)g_scratch + pre_off;
    float*       out = g_scratch + out_off;
    int row  = blockIdx.x;
    int t    = row & (TDIM - 1);
    int lane = threadIdx.x & 31;
    int h    = threadIdx.x >> 5;
    int c0   = h * 64 + lane;
    int c1   = c0 + 32;

    const float* p = pre + (size_t)row * DDIM;
    float v0 = bias[c0], v1 = bias[c1];
#pragma unroll
    for (int kk = 0; kk < 4; kk++) {
        int dt = kk - 3;
        if (t + dt >= 0) {
            const float* pr = p + (ptrdiff_t)dt * DDIM;
            v0 = fmaf(w[c0 * 4 + kk], pr[c0], v0);
            v1 = fmaf(w[c1 * 4 + kk], pr[c1], v1);
        }
    }
    v0 *= sigmoidf_(v0);
    v1 *= sigmoidf_(v1);
    if (do_norm) {
        float ss = v0 * v0 + v1 * v1;
#pragma unroll
        for (int o = 16; o > 0; o >>= 1) ss += __shfl_xor_sync(0xffffffffu, ss, o);
        float inv = 1.f / fmaxf(sqrtf(ss), 1e-6f);
        v0 *= inv; v1 *= inv;
    }
    out[(size_t)row * DDIM + c0] = v0;
    out[(size_t)row * DDIM + c1] = v1;
}

// ---------------------------------------------------------------------------
// prep_kernel: register-tiled dots + exp2 tables + register substitution.
// ---------------------------------------------------------------------------
__global__ __launch_bounds__(256) void prep_kernel()
{
    extern __shared__ float sm[];
    float* Kc  = sm;                 // [64][68]
    float* Qv  = sm + 4352;          // [64][68]  Q, then V, then Uv stage
    float* MM  = sm + 8704;          // [64][68]  M, then W stage
    float* sLc = sm + 13056;
    float* sLp = sm + 13120;
    float* sbv = sm + 13184;
    float* sbp = sm + 13248;
    float* E2  = sm + 13312;   // exp2(sLc[t]+104)
    float* Ei2 = sm + 13376;   // exp2(-sLc[i]-104)
    float* E2p = sm + 13440;   // exp2(sLp[i]+104)
    float* A0  = sm + 13504;   // exp2(sLc[t])
    float* G0  = sm + 13568;   // exp2(Lc63 - sLc[i])

    const float* Qn = g_scratch + OF_QN;
    const float* Kn = g_scratch + OF_KN;
    const float* Vn = g_scratch + OF_VN;
    const float* Al = g_scratch + OF_A;
    const float* Be = g_scratch + OF_B;

    int cid = blockIdx.x;
    int bh = cid >> 6, ci = cid & 63;
    int b = bh >> 4, h = bh & 15;
    int t0c = ci << 6;
    size_t base  = (size_t)b * TDIM * DDIM + (size_t)h * 64 + (size_t)t0c * DDIM;
    size_t abase = (size_t)b * TDIM * HDIM + h + (size_t)t0c * HDIM;
    int tid = threadIdx.x;

    if (tid < 64) {
        sLc[tid] = log2f(Al[abase + (size_t)tid * HDIM]);
        sbv[tid] = Be[abase + (size_t)tid * HDIM];
    }
    __syncthreads();
    if (tid == 0) {
        float run = 0.f;
        for (int i = 0; i < 64; i++) { sLp[i] = run; run += sLc[i]; sLc[i] = run; }
    }
    {
        int row = tid >> 4;
        int col = (tid & 15) << 2;
        for (int rr = 0; rr < 4; rr++) {
            int r = row + rr * 16;
            *(float4*)&Kc[r * 68 + col] = *(const float4*)(Kn + base + (size_t)r * DDIM + col);
            *(float4*)&Qv[r * 68 + col] = *(const float4*)(Qn + base + (size_t)r * DDIM + col);
        }
    }
    __syncthreads();
    if (tid < 64) {
        float lc = sLc[tid], lp = sLp[tid];
        sbp[tid] = sbv[tid] * exp2f(lp);
        E2[tid]  = exp2f(lc + 104.f);
        Ei2[tid] = exp2f(-lc - 104.f);
        E2p[tid] = exp2f(lp + 104.f);
        A0[tid]  = exp2f(lc);
        G0[tid]  = exp2f(sLc[63] - lc);
    }
    __syncthreads();

    float* Pg  = g_scratch + OF_PG  + (size_t)cid * 4096;
    float* AQg = g_scratch + OF_AQG + (size_t)cid * 4096;
    float* Gg  = g_scratch + OF_GKT + (size_t)cid * 4096;
    float* Wg  = g_scratch + OF_WTG + (size_t)cid * 4096;
    float* Ug  = g_scratch + OF_UVT + (size_t)cid * 4096;

    // AQ[t][k] and GkT[r][i] (elementwise scalings)
    for (int kq = 0; kq < 16; kq++) {
        int e = kq * 256 + tid;
        int t = e >> 6, i = e & 63;
        AQg[e] = A0[t] * Qv[t * 68 + i];
        Gg[e]  = G0[i] * Kc[i * 68 + t];
    }

    // P = (decay-scaled) Q.K^T, lower triangle, 4x4 register tiles.
    {
        int tt = tid >> 4, ti = tid & 15;
        int t0 = tt << 2, i0 = ti << 2;
        if (i0 <= t0 + 3) {
            ull acc2[4][4];
#pragma unroll
            for (int a = 0; a < 4; a++)
#pragma unroll
                for (int bb2 = 0; bb2 < 4; bb2++) acc2[a][bb2] = 0ull;
#pragma unroll 8
            for (int m = 0; m < 64; m += 2) {
                ull qr[4], kr[4];
#pragma unroll
                for (int a = 0; a < 4; a++) qr[a] = *(ull*)&Qv[(t0 + a) * 68 + m];
#pragma unroll
                for (int bb2 = 0; bb2 < 4; bb2++) kr[bb2] = *(ull*)&Kc[(i0 + bb2) * 68 + m];
#pragma unroll
                for (int a = 0; a < 4; a++)
#pragma unroll
                    for (int bb2 = 0; bb2 < 4; bb2++)
                        acc2[a][bb2] = fma2_(qr[a], kr[bb2], acc2[a][bb2]);
            }
#pragma unroll
            for (int a = 0; a < 4; a++) {
                int t = t0 + a;
                float4 v;
                float e2t = E2[t];
                v.x = (i0 + 0 <= t) ? e2t * Ei2[i0 + 0] * hadd2_(acc2[a][0]) : 0.f;
                v.y = (i0 + 1 <= t) ? e2t * Ei2[i0 + 1] * hadd2_(acc2[a][1]) : 0.f;
                v.z = (i0 + 2 <= t) ? e2t * Ei2[i0 + 2] * hadd2_(acc2[a][2]) : 0.f;
                v.w = (i0 + 3 <= t) ? e2t * Ei2[i0 + 3] * hadd2_(acc2[a][3]) : 0.f;
                *(float4*)(Pg + t * 64 + i0) = v;
            }
        } else {
            float4 z = make_float4(0.f, 0.f, 0.f, 0.f);
#pragma unroll
            for (int a = 0; a < 4; a++) *(float4*)(Pg + (t0 + a) * 64 + i0) = z;
        }
    }
    __syncthreads();
    // load V over Qv
    {
        int row = tid >> 4;
        int col = (tid & 15) << 2;
        for (int rr = 0; rr < 4; rr++) {
            int r = row + rr * 16;
            *(float4*)&Qv[r * 68 + col] = *(const float4*)(Vn + base + (size_t)r * DDIM + col);
        }
    }
    __syncthreads();
    // MM strictly lower, 4x4 register tiles
    {
        int tI = tid >> 4, tJ = tid & 15;
        int i0 = tI << 2, j0 = tJ << 2;
        if (j0 <= i0 + 3) {
            ull acc2[4][4];
#pragma unroll
            for (int a = 0; a < 4; a++)
#pragma unroll
                for (int bb2 = 0; bb2 < 4; bb2++) acc2[a][bb2] = 0ull;
#pragma unroll 8
            for (int m = 0; m < 64; m += 2) {
                ull ir[4], jr[4];
#pragma unroll
                for (int a = 0; a < 4; a++) ir[a] = *(ull*)&Kc[(i0 + a) * 68 + m];
#pragma unroll
                for (int bb2 = 0; bb2 < 4; bb2++) jr[bb2] = *(ull*)&Kc[(j0 + bb2) * 68 + m];
#pragma unroll
                for (int a = 0; a < 4; a++)
#pragma unroll
                    for (int bb2 = 0; bb2 < 4; bb2++)
                        acc2[a][bb2] = fma2_(ir[a], jr[bb2], acc2[a][bb2]);
            }
#pragma unroll
            for (int a = 0; a < 4; a++) {
                int i = i0 + a;
                float bi = sbv[i] * E2p[i];
#pragma unroll
                for (int bb2 = 0; bb2 < 4; bb2++) {
                    int j = j0 + bb2;
                    if (j < i)
                        MM[i * 68 + j] = bi * Ei2[j] * hadd2_(acc2[a][bb2]);
                }
            }
        }
    }
    __syncthreads();

    // register-resident forward substitution
    float xr[64];
    if (tid < 128) {
        int c = tid;
        if (c < 64) {
#pragma unroll
            for (int i = 0; i < 64; i++) xr[i] = sbv[i] * Qv[i * 68 + c];
        } else {
            int k = c - 64;
#pragma unroll
            for (int i = 0; i < 64; i++) xr[i] = sbp[i] * Kc[i * 68 + k];
        }
#pragma unroll
        for (int i = 1; i < 64; i++) {
            float a0 = 0.f, a1 = 0.f;
#pragma unroll
            for (int j = 0; j + 1 < i; j += 2) {
                a0 = fmaf(MM[i * 68 + j],     xr[j],     a0);
                a1 = fmaf(MM[i * 68 + j + 1], xr[j + 1], a1);
            }
            if (i & 1) a0 = fmaf(MM[i * 68 + (i - 1)], xr[i - 1], a0);
            xr[i] -= (a0 + a1);
        }
    }
    __syncthreads();
    if (tid < 64) {
        int c = tid;
#pragma unroll
        for (int i = 0; i < 64; i++) Qv[c * 68 + i] = xr[i];
    } else if (tid < 128) {
        int k = tid - 64;
#pragma unroll
        for (int i = 0; i < 64; i++) MM[i * 68 + k] = xr[i];
    }
    __syncthreads();
    for (int kq = 0; kq < 16; kq++) {
        int e = kq * 256 + tid;
        { int c = e >> 6, i = e & 63; Ug[e] = Qv[c * 68 + i]; }
        { int i = e >> 6, kk = e & 63; Wg[e] = MM[i * 68 + kk]; }
    }
    if (tid == 0) g_scratch[OF_ACG + cid] = exp2f(sLc[63]);
}

// ---------------------------------------------------------------------------
// scan_kernel (unchanged from round-13 winner)
// ---------------------------------------------------------------------------
__global__ __launch_bounds__(128) void scan_kernel()
{
    extern __shared__ float sm[];
    float* mW  = sm;
    float* mAQ = sm + 4352;
    float* mP  = sm + 8704;
    float* mG  = sm + 13056;
    float* S_T = sm + 17408;
    float* U_T = sm + 18496;

    int blk = blockIdx.x;
    int bh = blk >> 2, cq = blk & 3;
    int c0 = cq << 4;
    int b = bh >> 4, h = bh & 15;
    size_t obase = (size_t)b * TDIM * DDIM + (size_t)h * 64;
    int tid = threadIdx.x;
    int cc = tid & 15, grp = tid >> 4;

    for (int e = tid; e < 16 * 68; e += 128) S_T[e] = 0.f;
    __syncthreads();

    float* O = g_scratch + OF_O;

    for (int ch = 0; ch < NCHUNK; ch++) {
        int cid = bh * 64 + ch;
        const float* Wg  = g_scratch + OF_WTG + (size_t)cid * 4096;
        const float* AQg = g_scratch + OF_AQG + (size_t)cid * 4096;
        const float* Pg  = g_scratch + OF_PG  + (size_t)cid * 4096;
        const float* Gg  = g_scratch + OF_GKT + (size_t)cid * 4096;
        const float* Ug  = g_scratch + OF_UVT + (size_t)cid * 4096;

        for (int kq = 0; kq < 8; kq++) {
            int e4 = kq * 128 + tid;
            int r = e4 >> 4, c4 = (e4 & 15) << 2;
            *(float4*)&mW[r * 68 + c4]  = *(const float4*)(Wg  + r * 64 + c4);
            *(float4*)&mAQ[r * 68 + c4] = *(const float4*)(AQg + r * 64 + c4);
            *(float4*)&mP[r * 68 + c4]  = *(const float4*)(Pg  + r * 64 + c4);
            *(float4*)&mG[r * 68 + c4]  = *(const float4*)(Gg  + r * 64 + c4);
        }
        for (int kq = 0; kq < 2; kq++) {
            int e4 = kq * 128 + tid;
            int r = e4 >> 4, c4 = (e4 & 15) << 2;
            *(float4*)&U_T[r * 68 + c4] = *(const float4*)(Ug + (size_t)(c0 + r) * 64 + c4);
        }
        float AC = g_scratch[OF_ACG + cid];
        __syncthreads();

        {
            ull aU[8][2];
#pragma unroll
            for (int ii = 0; ii < 8; ii++) { aU[ii][0] = 0; aU[ii][1] = 0; }
#pragma unroll
            for (int k4 = 0; k4 < 16; k4++) {
                ull s01 = *(ull*)&S_T[cc * 68 + k4 * 4];
                ull s23 = *(ull*)&S_T[cc * 68 + k4 * 4 + 2];
#pragma unroll
                for (int ii = 0; ii < 8; ii++) {
                    int i = grp * 8 + ii;
                    aU[ii][0] = fma2_(*(ull*)&mW[i * 68 + k4 * 4],     s01, aU[ii][0]);
                    aU[ii][1] = fma2_(*(ull*)&mW[i * 68 + k4 * 4 + 2], s23, aU[ii][1]);
                }
            }
#pragma unroll
            for (int ii = 0; ii < 8; ii++) {
                int i = grp * 8 + ii;
                U_T[cc * 68 + i] -= (hadd2_(aU[ii][0]) + hadd2_(aU[ii][1]));
            }
        }
        float oacc[8];
        {
            ull aO[8][2];
#pragma unroll
            for (int ii = 0; ii < 8; ii++) { aO[ii][0] = 0; aO[ii][1] = 0; }
#pragma unroll
            for (int k4 = 0; k4 < 16; k4++) {
                ull s01 = *(ull*)&S_T[cc * 68 + k4 * 4];
                ull s23 = *(ull*)&S_T[cc * 68 + k4 * 4 + 2];
#pragma unroll
                for (int ii = 0; ii < 8; ii++) {
                    int t = grp * 8 + ii;
                    aO[ii][0] = fma2_(*(ull*)&mAQ[t * 68 + k4 * 4],     s01, aO[ii][0]);
                    aO[ii][1] = fma2_(*(ull*)&mAQ[t * 68 + k4 * 4 + 2], s23, aO[ii][1]);
                }
            }
#pragma unroll
            for (int ii = 0; ii < 8; ii++)
                oacc[ii] = hadd2_(aO[ii][0]) + hadd2_(aO[ii][1]);
        }
        __syncthreads();
        {
            ull aO[8][2];
#pragma unroll
            for (int ii = 0; ii < 8; ii++) { aO[ii][0] = 0; aO[ii][1] = 0; }
#pragma unroll
            for (int k4 = 0; k4 < 16; k4++) {
                ull u01 = *(ull*)&U_T[cc * 68 + k4 * 4];
                ull u23 = *(ull*)&U_T[cc * 68 + k4 * 4 + 2];
#pragma unroll
                for (int ii = 0; ii < 8; ii++) {
                    int t = grp * 8 + ii;
                    aO[ii][0] = fma2_(*(ull*)&mP[t * 68 + k4 * 4],     u01, aO[ii][0]);
                    aO[ii][1] = fma2_(*(ull*)&mP[t * 68 + k4 * 4 + 2], u23, aO[ii][1]);
                }
            }
#pragma unroll
            for (int ii = 0; ii < 8; ii++) {
                int t = grp * 8 + ii;
                float ov = oacc[ii] + hadd2_(aO[ii][0]) + hadd2_(aO[ii][1]);
                O[obase + (size_t)(ch * 64 + t) * DDIM + c0 + cc] = ov;
            }
        }
        {
            ull aS[8][2];
#pragma unroll
            for (int ii = 0; ii < 8; ii++) { aS[ii][0] = 0; aS[ii][1] = 0; }
#pragma unroll
            for (int k4 = 0; k4 < 16; k4++) {
                ull u01 = *(ull*)&U_T[cc * 68 + k4 * 4];
                ull u23 = *(ull*)&U_T[cc * 68 + k4 * 4 + 2];
#pragma unroll
                for (int ii = 0; ii < 8; ii++) {
                    int r = grp * 8 + ii;
                    aS[ii][0] = fma2_(*(ull*)&mG[r * 68 + k4 * 4],     u01, aS[ii][0]);
                    aS[ii][1] = fma2_(*(ull*)&mG[r * 68 + k4 * 4 + 2], u23, aS[ii][1]);
                }
            }
#pragma unroll
            for (int ii = 0; ii < 8; ii++) {
                int r = grp * 8 + ii;
                S_T[cc * 68 + r] = AC * S_T[cc * 68 + r]
                                   + hadd2_(aS[ii][0]) + hadd2_(aS[ii][1]);
            }
        }
        __syncthreads();
    }
}

__global__ __launch_bounds__(512) void post_kernel(const float* __restrict__ rms_w)
{
    const float* O  = g_scratch + OF_O;
    const float* G  = g_scratch + OF_G;
    float*       Og = g_scratch + OF_OG;
    int row  = blockIdx.x;
    int lane = threadIdx.x & 31;
    int h    = threadIdx.x >> 5;
    size_t i0 = (size_t)row * DDIM + h * 64 + lane;
    float v0 = O[i0], v1 = O[i0 + 32];
    float ss = v0 * v0 + v1 * v1;
#pragma unroll
    for (int o = 16; o > 0; o >>= 1) ss += __shfl_xor_sync(0xffffffffu, ss, o);
    float inv = rsqrtf(ss * (1.f / 64.f) + 1e-6f);
    v0 = v0 * inv * rms_w[h * 64 + lane]      * G[i0];
    v1 = v1 * inv * rms_w[h * 64 + lane + 32] * G[i0 + 32];
    Og[i0]      = v0;
    Og[i0 + 32] = v1;
}

extern "C" void kernel_launch(void* const* d_in, const int* in_sizes, int n_in,
                              void* d_out, int out_size)
{
    (void)in_sizes; (void)n_in; (void)out_size;
    const float* x   = (const float*)d_in[0];
    const float* Wq  = (const float*)d_in[1];
    const float* Wk  = (const float*)d_in[2];
    const float* Wv  = (const float*)d_in[3];
    const float* Wo  = (const float*)d_in[4];
    const float* Wa  = (const float*)d_in[5];
    const float* ba  = (const float*)d_in[6];
    const float* Wb  = (const float*)d_in[7];
    const float* bb  = (const float*)d_in[8];
    const float* Wgd = (const float*)d_in[9];
    const float* Wgu = (const float*)d_in[10];
    const float* rms = (const float*)d_in[11];
    const float* qcw = (const float*)d_in[12];
    const float* qcb = (const float*)d_in[13];
    const float* kcw = (const float*)d_in[14];
    const float* kcb = (const float*)d_in[15];
    const float* vcw = (const float*)d_in[16];
    const float* vcb = (const float*)d_in[17];
    float* out = (float*)d_out;

    cudaFuncSetAttribute(prep_kernel, cudaFuncAttributeMaxDynamicSharedMemorySize, 57344);
    cudaFuncSetAttribute(scan_kernel, cudaFuncAttributeMaxDynamicSharedMemorySize, 81920);

    // 1) alpha/beta
    ab_kernel<<<MROWS / 8, 256>>>(x, Wa, ba, Wb, bb);
    // 2) fused QKV projection
    {
        dim3 gqkv(24, MROWS / 128);
        gemm_tc<<<gqkv, 256>>>(x, 0, Wq, Wk, Wv, nullptr, OF_Q, 8,
                               MROWS, 1024, 1024, 0);
    }
    // 3) conv
    {
        dim3 gc(MROWS, 3);
        conv_kernel<<<gc, 512>>>(qcw, qcb, kcw, kcb, vcw, vcb);
    }
    // 4) chunk prep (parallel)  <-- ncu capture slot
    prep_kernel<<<NCH_TOT, 256, 57344>>>();
    // 5) chunk scan
    scan_kernel<<<BDIM * HDIM * 4, 128, 81920>>>();
    // 6-7) gate MLP
    {
        dim3 g512g(4, MROWS / 128);
        gemm_tc<<<g512g, 256>>>(x, 0, Wgd, Wgd, Wgd, nullptr, OF_XG, 4,
                                MROWS, 512, 1024, 1);
    }
    {
        dim3 g1024g(8, MROWS / 128);
        gemm_tc<<<g1024g, 256>>>(nullptr, OF_XG, Wgu, Wgu, Wgu, nullptr, OF_G, 8,
                                 MROWS, 1024, 512, 2);
    }
    // 8) RMSNorm + gate
    post_kernel<<<MROWS, 512>>>(rms);
    // 9) output projection
    {
        dim3 g1024g(8, MROWS / 128);
        gemm_tc<<<g1024g, 256>>>(nullptr, OF_OG, Wo, Wo, Wo, out, 0, 8,
                                 MROWS, 1024, 1024, 0);
    }
}